// round 4
// baseline (speedup 1.0000x reference)
#include <cuda_runtime.h>
#include <math.h>

// Problem constants (hardcoded; reference: B=2, S=2048, D=2048, H=16, DK=128)
#define B_  2
#define S_  2048
#define D_  2048
#define H_  16
#define DK_ 128
#define M_  (B_ * S_)                     // 4096 rows for projection GEMMs

static const size_t OUT_N  = (size_t)B_ * S_ * D_;        // 8388608
static const size_t ATTN_N = (size_t)B_ * H_ * S_ * S_;   // 134217728

// ---------------------------------------------------------------------------
// Scratch: __device__ globals (allocation-free contract).
// attn scores live in the d_out attn region when present; fallback otherwise.
// ---------------------------------------------------------------------------
__device__ float g_q[B_ * H_ * S_ * DK_];   // [B,H,S,DK]
__device__ float g_k[B_ * H_ * S_ * DK_];
__device__ float g_v[B_ * H_ * S_ * DK_];
__device__ float g_x[B_ * S_ * D_];         // attention out, [B,S,D] layout
__device__ float g_attn_fb[(size_t)B_ * H_ * S_ * S_];  // fallback scores buffer

// ---------------------------------------------------------------------------
// K1/K5: C = A[M,K] @ W[N,K]^T + bias   (NT GEMM, both K-contiguous)
// BHSD=true scatters C[m][n] into [B,H,S,DK] layout (for Q/K/V projections).
// 128x128 block tile, BK=16, 256 threads, 8x8 per-thread microtile.
// ---------------------------------------------------------------------------
template <bool BHSD>
__global__ void __launch_bounds__(256)
gemm_nt_kernel(const float* __restrict__ A, const float* __restrict__ W,
               const float* __restrict__ bias, float* __restrict__ C,
               int M, int N, int K)
{
    const int BM = 128, BN = 128, BK = 16;
    __shared__ float As[BK][BM];   // transposed: As[k][m]
    __shared__ float Ws[BK][BN];   // transposed: Ws[k][n]

    const int bm = blockIdx.y, bn = blockIdx.x;
    const int tid = threadIdx.x;
    const int tx = tid & 15, ty = tid >> 4;   // 16x16 thread grid

    float acc[8][8];
#pragma unroll
    for (int i = 0; i < 8; i++)
#pragma unroll
        for (int j = 0; j < 8; j++) acc[i][j] = 0.0f;

    const int a0 = bm * BM;
    const int w0 = bn * BN;

    for (int k0 = 0; k0 < K; k0 += BK) {
#pragma unroll
        for (int l = 0; l < 2; l++) {
            int id  = tid + l * 256;          // 512 float4 per tile
            int row = id >> 2;                // 0..127
            int kc  = (id & 3) * 4;           // 0,4,8,12
            float4 va = *(const float4*)(A + (size_t)(a0 + row) * K + k0 + kc);
            As[kc + 0][row] = va.x; As[kc + 1][row] = va.y;
            As[kc + 2][row] = va.z; As[kc + 3][row] = va.w;
            float4 vw = *(const float4*)(W + (size_t)(w0 + row) * K + k0 + kc);
            Ws[kc + 0][row] = vw.x; Ws[kc + 1][row] = vw.y;
            Ws[kc + 2][row] = vw.z; Ws[kc + 3][row] = vw.w;
        }
        __syncthreads();

#pragma unroll
        for (int k = 0; k < BK; k++) {
            float a[8], b[8];
#pragma unroll
            for (int i = 0; i < 8; i++) a[i] = As[k][ty * 8 + i];
#pragma unroll
            for (int j = 0; j < 8; j++) b[j] = Ws[k][tx * 8 + j];
#pragma unroll
            for (int i = 0; i < 8; i++)
#pragma unroll
                for (int j = 0; j < 8; j++) acc[i][j] += a[i] * b[j];
        }
        __syncthreads();
    }

#pragma unroll
    for (int i = 0; i < 8; i++) {
        int m = a0 + ty * 8 + i;
#pragma unroll
        for (int j = 0; j < 8; j++) {
            int n = w0 + tx * 8 + j;
            float v = acc[i][j] + bias[n];
            if (BHSD) {
                int b  = m / S_, s  = m % S_;
                int h  = n / DK_, dk = n % DK_;
                C[(((size_t)b * H_ + h) * S_ + s) * DK_ + dk] = v;
            } else {
                C[(size_t)m * N + n] = v;
            }
        }
    }
}

// ---------------------------------------------------------------------------
// K2: raw causal scores  S = Q @ K^T * scale   per (b,h)
// Skips tiles entirely above the diagonal. Garbage above the diagonal inside
// diagonal tiles is overwritten with zeros by the softmax kernel.
// ---------------------------------------------------------------------------
__global__ void __launch_bounds__(256)
scores_kernel(const float* __restrict__ Qm, const float* __restrict__ Km,
              float* __restrict__ attn, float scale)
{
    const int BM = 128, BN = 128, BK = 16;
    const int bm = blockIdx.y, bn = blockIdx.x, z = blockIdx.z;
    if (bn * BN > bm * BM + (BM - 1)) return;   // fully masked tile

    const float* A = Qm + (size_t)z * S_ * DK_;
    const float* W = Km + (size_t)z * S_ * DK_;
    float*       C = attn + (size_t)z * S_ * S_;

    __shared__ float As[BK][BM];
    __shared__ float Ws[BK][BN];

    const int tid = threadIdx.x;
    const int tx = tid & 15, ty = tid >> 4;

    float acc[8][8];
#pragma unroll
    for (int i = 0; i < 8; i++)
#pragma unroll
        for (int j = 0; j < 8; j++) acc[i][j] = 0.0f;

    const int a0 = bm * BM;
    const int w0 = bn * BN;

    for (int k0 = 0; k0 < DK_; k0 += BK) {
#pragma unroll
        for (int l = 0; l < 2; l++) {
            int id  = tid + l * 256;
            int row = id >> 2;
            int kc  = (id & 3) * 4;
            float4 va = *(const float4*)(A + (size_t)(a0 + row) * DK_ + k0 + kc);
            As[kc + 0][row] = va.x; As[kc + 1][row] = va.y;
            As[kc + 2][row] = va.z; As[kc + 3][row] = va.w;
            float4 vw = *(const float4*)(W + (size_t)(w0 + row) * DK_ + k0 + kc);
            Ws[kc + 0][row] = vw.x; Ws[kc + 1][row] = vw.y;
            Ws[kc + 2][row] = vw.z; Ws[kc + 3][row] = vw.w;
        }
        __syncthreads();

#pragma unroll
        for (int k = 0; k < BK; k++) {
            float a[8], b[8];
#pragma unroll
            for (int i = 0; i < 8; i++) a[i] = As[k][ty * 8 + i];
#pragma unroll
            for (int j = 0; j < 8; j++) b[j] = Ws[k][tx * 8 + j];
#pragma unroll
            for (int i = 0; i < 8; i++)
#pragma unroll
                for (int j = 0; j < 8; j++) acc[i][j] += a[i] * b[j];
        }
        __syncthreads();
    }

#pragma unroll
    for (int i = 0; i < 8; i++) {
        int m = a0 + ty * 8 + i;
#pragma unroll
        for (int j = 0; j < 8; j++) {
            int n = w0 + tx * 8 + j;
            C[(size_t)m * S_ + n] = acc[i][j] * scale;
        }
    }
}

// ---------------------------------------------------------------------------
// K3: causal softmax, one block per (b,h,q) row; in-place on scores.
// Writes exact zeros above the diagonal (matches exp(-1e9-max) underflow).
// ---------------------------------------------------------------------------
__global__ void __launch_bounds__(256)
softmax_kernel(float* __restrict__ attn)
{
    const int r   = blockIdx.x;          // 0 .. B*H*S-1
    const int z   = r / S_;
    const int q   = r % S_;
    float* row = attn + (size_t)z * S_ * S_ + (size_t)q * S_;
    const int len = q + 1;
    const int tid = threadIdx.x;
    const int lane = tid & 31, wid = tid >> 5;

    __shared__ float smax[8];
    __shared__ float ssum[8];

    // row max
    float m = -3.0e38f;
    for (int i = tid; i < len; i += 256) m = fmaxf(m, row[i]);
#pragma unroll
    for (int o = 16; o > 0; o >>= 1) m = fmaxf(m, __shfl_xor_sync(0xffffffffu, m, o));
    if (lane == 0) smax[wid] = m;
    __syncthreads();
    float bmax = smax[0];
#pragma unroll
    for (int w = 1; w < 8; w++) bmax = fmaxf(bmax, smax[w]);

    // sum of exp
    float s = 0.0f;
    for (int i = tid; i < len; i += 256) s += expf(row[i] - bmax);
#pragma unroll
    for (int o = 16; o > 0; o >>= 1) s += __shfl_xor_sync(0xffffffffu, s, o);
    if (lane == 0) ssum[wid] = s;
    __syncthreads();
    float bsum = 0.0f;
#pragma unroll
    for (int w = 0; w < 8; w++) bsum += ssum[w];
    const float inv = 1.0f / bsum;

    for (int i = tid; i < len; i += 256) row[i] = expf(row[i] - bmax) * inv;
    for (int i = len + tid; i < S_; i += 256) row[i] = 0.0f;
}

// ---------------------------------------------------------------------------
// K4: X = attn @ V per (b,h), NN GEMM, k-loop truncated at the diagonal.
// Output written directly in [B,S,D] layout so the O-projection is a plain GEMM.
// ---------------------------------------------------------------------------
__global__ void __launch_bounds__(256)
pv_kernel(const float* __restrict__ attn, const float* __restrict__ Vm,
          float* __restrict__ Xbsd)
{
    const int BM = 128, BK = 16;          // BN == DK_ == 128
    const int bm = blockIdx.y, z = blockIdx.z;
    const int b = z / H_, h = z % H_;
    const float* A = attn + (size_t)z * S_ * S_;   // [S, S]
    const float* V = Vm   + (size_t)z * S_ * DK_;  // [S, 128]

    __shared__ float As[BK][BM];   // As[k][m]
    __shared__ float Bs[BK][DK_];  // Bs[k][n]

    const int tid = threadIdx.x;
    const int tx = tid & 15, ty = tid >> 4;

    float acc[8][8];
#pragma unroll
    for (int i = 0; i < 8; i++)
#pragma unroll
        for (int j = 0; j < 8; j++) acc[i][j] = 0.0f;

    const int a0 = bm * BM;
    const int kend = (bm + 1) * BM;       // causal: keys <= last query in tile

    for (int k0 = 0; k0 < kend; k0 += BK) {
#pragma unroll
        for (int l = 0; l < 2; l++) {
            int id  = tid + l * 256;
            int row = id >> 2;
            int kc  = (id & 3) * 4;
            float4 va = *(const float4*)(A + (size_t)(a0 + row) * S_ + k0 + kc);
            As[kc + 0][row] = va.x; As[kc + 1][row] = va.y;
            As[kc + 2][row] = va.z; As[kc + 3][row] = va.w;

            int kr = id >> 5;             // 0..15
            int nc = (id & 31) * 4;       // 0..124
            *(float4*)&Bs[kr][nc] = *(const float4*)(V + (size_t)(k0 + kr) * DK_ + nc);
        }
        __syncthreads();

#pragma unroll
        for (int k = 0; k < BK; k++) {
            float a[8], b8[8];
#pragma unroll
            for (int i = 0; i < 8; i++) a[i] = As[k][ty * 8 + i];
#pragma unroll
            for (int j = 0; j < 8; j++) b8[j] = Bs[k][tx * 8 + j];
#pragma unroll
            for (int i = 0; i < 8; i++)
#pragma unroll
                for (int j = 0; j < 8; j++) acc[i][j] += a[i] * b8[j];
        }
        __syncthreads();
    }

#pragma unroll
    for (int i = 0; i < 8; i++) {
        int s = a0 + ty * 8 + i;
#pragma unroll
        for (int j = 0; j < 8; j++) {
            int dk = tx * 8 + j;
            Xbsd[((size_t)b * S_ + s) * D_ + h * DK_ + dk] = acc[i][j];
        }
    }
}

// ---------------------------------------------------------------------------
// Launch
// ---------------------------------------------------------------------------
extern "C" void kernel_launch(void* const* d_in, const int* in_sizes, int n_in,
                              void* d_out, int out_size)
{
    const float* query = (const float*)d_in[0];
    const float* key   = (const float*)d_in[1];
    const float* value = (const float*)d_in[2];
    const float* Wq    = (const float*)d_in[3];
    const float* bq    = (const float*)d_in[4];
    const float* Wk    = (const float*)d_in[5];
    const float* bk    = (const float*)d_in[6];
    const float* Wv    = (const float*)d_in[7];
    const float* bv    = (const float*)d_in[8];
    const float* Wo    = (const float*)d_in[9];
    const float* bo    = (const float*)d_in[10];
    float* out = (float*)d_out;

    // resolve scratch symbols (host API, not stream-ordered: capture-safe)
    float *pq, *pk, *pv, *px, *pfb;
    cudaGetSymbolAddress((void**)&pq,  g_q);
    cudaGetSymbolAddress((void**)&pk,  g_k);
    cudaGetSymbolAddress((void**)&pv,  g_v);
    cudaGetSymbolAddress((void**)&px,  g_x);
    cudaGetSymbolAddress((void**)&pfb, g_attn_fb);

    // attn lives in d_out (reference returns (out, attn)); fallback otherwise
    float* attn = ((size_t)out_size >= OUT_N + ATTN_N) ? (out + OUT_N) : pfb;

    dim3 blk(256);
    dim3 gproj(D_ / 128, M_ / 128);            // (16, 32)

    // 1) QKV projections -> [B,H,S,DK]
    gemm_nt_kernel<true><<<gproj, blk>>>(query, Wq, bq, pq, M_, D_, D_);
    gemm_nt_kernel<true><<<gproj, blk>>>(key,   Wk, bk, pk, M_, D_, D_);
    gemm_nt_kernel<true><<<gproj, blk>>>(value, Wv, bv, pv, M_, D_, D_);

    // 2) raw causal scores (in the attn output region)
    const float scale = 1.0f / sqrtf((float)DK_);   // 1/sqrt(128)
    dim3 gsc(S_ / 128, S_ / 128, B_ * H_);          // (16, 16, 32)
    scores_kernel<<<gsc, blk>>>(pq, pk, attn, scale);

    // 3) causal softmax in place (also zero-fills masked region)
    softmax_kernel<<<B_ * H_ * S_, blk>>>(attn);

    // 4) X = attn @ V  -> [B,S,D]
    dim3 gpv(1, S_ / 128, B_ * H_);
    pv_kernel<<<gpv, blk>>>(attn, pv, px);

    // 5) out = X @ Wo^T + bo
    gemm_nt_kernel<false><<<gproj, blk>>>(px, Wo, bo, out, M_, D_, D_);
}

// round 10
// speedup vs baseline: 1.5563x; 1.5563x over previous
#include <cuda_runtime.h>
#include <cuda_bf16.h>
#include <math.h>
#include <stdint.h>

// Problem constants (B=2, S=2048, D=2048, H=16, DK=128)
#define B_  2
#define S_  2048
#define D_  2048
#define H_  16
#define DK_ 128
#define M_  (B_ * S_)                     // 4096 rows for projection GEMMs

static const size_t OUT_N  = (size_t)B_ * S_ * D_;        // 8388608
static const size_t ATTN_N = (size_t)B_ * H_ * S_ * S_;   // 134217728

// ---------------------------------------------------------------------------
// Scratch (__device__ globals; allocation-free contract)
// ---------------------------------------------------------------------------
__device__ float g_q[B_ * H_ * S_ * DK_];   // [B,H,S,DK] fp32
__device__ float g_k[B_ * H_ * S_ * DK_];
__device__ float g_v[B_ * H_ * S_ * DK_];
__device__ float g_x[B_ * S_ * D_];         // attention out [B,S,D] fp32
__device__ float g_attn_fb[(size_t)B_ * H_ * S_ * S_];  // fallback scores

// bf16 split operands for tensor-core projections
__device__ __nv_bfloat16 g_qi_h[M_ * D_], g_qi_l[M_ * D_];
__device__ __nv_bfloat16 g_ki_h[M_ * D_], g_ki_l[M_ * D_];
__device__ __nv_bfloat16 g_vi_h[M_ * D_], g_vi_l[M_ * D_];
__device__ __nv_bfloat16 g_x_h [M_ * D_], g_x_l [M_ * D_];
__device__ __nv_bfloat16 g_wq_h[D_ * D_], g_wq_l[D_ * D_];
__device__ __nv_bfloat16 g_wk_h[D_ * D_], g_wk_l[D_ * D_];
__device__ __nv_bfloat16 g_wv_h[D_ * D_], g_wv_l[D_ * D_];
__device__ __nv_bfloat16 g_wo_h[D_ * D_], g_wo_l[D_ * D_];

// ---------------------------------------------------------------------------
// Baseline-ISA helpers (sm_80-level: cp.async / ldmatrix / mma.sync only)
// ---------------------------------------------------------------------------
__device__ __forceinline__ uint32_t smem_u32(const void* p) {
    uint32_t a;
    asm("{ .reg .u64 t; cvta.to.shared.u64 t, %1; cvt.u32.u64 %0, t; }"
        : "=r"(a) : "l"(p));
    return a;
}
__device__ __forceinline__ void cpa16(uint32_t saddr, const void* g) {
    asm volatile("cp.async.cg.shared.global [%0], [%1], 16;"
                 :: "r"(saddr), "l"(g));
}
#define CP_COMMIT() asm volatile("cp.async.commit_group;" ::: "memory")
#define CP_WAIT1()  asm volatile("cp.async.wait_group 1;" ::: "memory")
#define CP_WAIT0()  asm volatile("cp.async.wait_group 0;" ::: "memory")

__device__ __forceinline__ void ldmx4(uint32_t& r0, uint32_t& r1,
                                      uint32_t& r2, uint32_t& r3, uint32_t addr) {
    asm volatile("ldmatrix.sync.aligned.m8n8.x4.shared.b16 {%0,%1,%2,%3}, [%4];"
                 : "=r"(r0), "=r"(r1), "=r"(r2), "=r"(r3) : "r"(addr));
}
__device__ __forceinline__ void mma16816(float* c, uint32_t a0, uint32_t a1,
                                         uint32_t a2, uint32_t a3,
                                         uint32_t b0, uint32_t b1) {
    asm volatile(
        "mma.sync.aligned.m16n8k16.row.col.f32.bf16.bf16.f32 "
        "{%0,%1,%2,%3}, {%4,%5,%6,%7}, {%8,%9}, {%0,%1,%2,%3};"
        : "+f"(c[0]), "+f"(c[1]), "+f"(c[2]), "+f"(c[3])
        : "r"(a0), "r"(a1), "r"(a2), "r"(a3), "r"(b0), "r"(b1));
}

// ---------------------------------------------------------------------------
// K0: fp32 -> (bf16 hi, bf16 lo) split, vectorized
// ---------------------------------------------------------------------------
__global__ void __launch_bounds__(256)
split_kernel(const float* __restrict__ x, __nv_bfloat16* __restrict__ hi,
             __nv_bfloat16* __restrict__ lo, int n4)
{
    int i = blockIdx.x * 256 + threadIdx.x;
    int stride = gridDim.x * 256;
    for (; i < n4; i += stride) {
        float4 v = ((const float4*)x)[i];
        __nv_bfloat16 h0 = __float2bfloat16(v.x);
        __nv_bfloat16 h1 = __float2bfloat16(v.y);
        __nv_bfloat16 h2 = __float2bfloat16(v.z);
        __nv_bfloat16 h3 = __float2bfloat16(v.w);
        __nv_bfloat16 l0 = __float2bfloat16(v.x - __bfloat162float(h0));
        __nv_bfloat16 l1 = __float2bfloat16(v.y - __bfloat162float(h1));
        __nv_bfloat16 l2 = __float2bfloat16(v.z - __bfloat162float(h2));
        __nv_bfloat16 l3 = __float2bfloat16(v.w - __bfloat162float(h3));
        ((__nv_bfloat162*)hi)[2 * i]     = __nv_bfloat162(h0, h1);
        ((__nv_bfloat162*)hi)[2 * i + 1] = __nv_bfloat162(h2, h3);
        ((__nv_bfloat162*)lo)[2 * i]     = __nv_bfloat162(l0, l1);
        ((__nv_bfloat162*)lo)[2 * i + 1] = __nv_bfloat162(l2, l3);
    }
}

// ---------------------------------------------------------------------------
// K1: mma.sync projection GEMM  C = A[M,K] @ W[N,K]^T + bias
// Split-fp32: 3 passes (Ah*Wh, Ah*Wl, Al*Wh) accumulated in fp32 registers.
// 128x128 CTA tile, BK=32, 8 warps (2x4), warp tile 64x32, cp.async 2-stage.
// BHSD=1 scatters to [B,H,S,DK] (Q/K/V); BHSD=0 writes [M,N] (O proj).
// ---------------------------------------------------------------------------
#define BMT  128
#define BNT  128
#define BKT  32
#define PADK 40              // bf16 elems per smem row (32 + 8 pad)
#define NSTG 192             // 3 passes * 64 k-chunks

__global__ void __launch_bounds__(256, 2)
gemm_mma(const __nv_bfloat16* __restrict__ Ahi, const __nv_bfloat16* __restrict__ Alo,
         const __nv_bfloat16* __restrict__ Whi, const __nv_bfloat16* __restrict__ Wlo,
         const float* __restrict__ bias, float* __restrict__ C, int bhsd)
{
    __shared__ __nv_bfloat16 As[2][BMT][PADK];
    __shared__ __nv_bfloat16 Bs[2][BNT][PADK];

    const int tid  = threadIdx.x;
    const int lane = tid & 31, wid = tid >> 5;
    const int wm = wid & 1;          // 0..1  (m-warps, 64 rows each)
    const int wn = wid >> 1;         // 0..3  (n-warps, 32 cols each)
    const int a0 = blockIdx.y * BMT;
    const int n0 = blockIdx.x * BNT;

    const __nv_bfloat16* Ap[3] = { Ahi, Ahi, Alo };
    const __nv_bfloat16* Wp[3] = { Whi, Wlo, Whi };

    float acc[4][4][4];
#pragma unroll
    for (int i = 0; i < 4; i++)
#pragma unroll
        for (int j = 0; j < 4; j++)
#pragma unroll
            for (int k = 0; k < 4; k++) acc[i][j][k] = 0.0f;

    // load indexing: each thread loads 32B of one A row and one B row
    const int lrow = tid >> 1;              // 0..127
    const int lseg = (tid & 1) * 2;         // 16B-seg 0 or 2

    auto load_stage = [&](int st, int s) {
        const int p  = st >> 6;
        const int k0 = (st & 63) * BKT;
        const __nv_bfloat16* A = Ap[p];
        const __nv_bfloat16* W = Wp[p];
        uint32_t sa = smem_u32(&As[s][lrow][lseg * 8]);
        const __nv_bfloat16* ga = A + (size_t)(a0 + lrow) * D_ + k0 + lseg * 8;
        cpa16(sa,      ga);
        cpa16(sa + 16, ga + 8);
        uint32_t sb = smem_u32(&Bs[s][lrow][lseg * 8]);
        const __nv_bfloat16* gw = W + (size_t)(n0 + lrow) * D_ + k0 + lseg * 8;
        cpa16(sb,      gw);
        cpa16(sb + 16, gw + 8);
    };

    load_stage(0, 0); CP_COMMIT();
    load_stage(1, 1); CP_COMMIT();

    for (int st = 0; st < NSTG; ++st) {
        const int s = st & 1;
        if (st + 1 < NSTG) CP_WAIT1(); else CP_WAIT0();
        __syncthreads();

        // B fragments: 4 n8-blocks, each x4 covers k0..31
        uint32_t bf[4][4];
#pragma unroll
        for (int ni = 0; ni < 4; ++ni) {
            uint32_t addr = smem_u32(
                &Bs[s][wn * 32 + ni * 8 + (lane & 7)][(lane >> 3) * 8]);
            ldmx4(bf[ni][0], bf[ni][1], bf[ni][2], bf[ni][3], addr);
        }
#pragma unroll
        for (int k16 = 0; k16 < 2; ++k16) {
#pragma unroll
            for (int mi = 0; mi < 4; ++mi) {
                uint32_t fa0, fa1, fa2, fa3;
                uint32_t addr = smem_u32(
                    &As[s][wm * 64 + mi * 16 + (lane & 15)]
                          [(lane >> 4) * 8 + k16 * 16]);
                ldmx4(fa0, fa1, fa2, fa3, addr);
#pragma unroll
                for (int ni = 0; ni < 4; ++ni)
                    mma16816(acc[mi][ni], fa0, fa1, fa2, fa3,
                             bf[ni][k16 * 2], bf[ni][k16 * 2 + 1]);
            }
        }
        __syncthreads();
        if (st + 2 < NSTG) { load_stage(st + 2, s); CP_COMMIT(); }
    }

    // epilogue
#pragma unroll
    for (int mi = 0; mi < 4; ++mi) {
#pragma unroll
        for (int ni = 0; ni < 4; ++ni) {
            int r = wm * 64 + mi * 16 + (lane >> 2);
            int c = wn * 32 + ni * 8 + (lane & 3) * 2;
            int n = n0 + c;
            float2 v0, v1;
            v0.x = acc[mi][ni][0] + bias[n];
            v0.y = acc[mi][ni][1] + bias[n + 1];
            v1.x = acc[mi][ni][2] + bias[n];
            v1.y = acc[mi][ni][3] + bias[n + 1];
            int m0 = a0 + r, m1 = m0 + 8;
            if (bhsd) {
                int h = n >> 7, dk = n & 127;
                int b0v = m0 >> 11, s0 = m0 & (S_ - 1);
                int b1v = m1 >> 11, s1 = m1 & (S_ - 1);
                *(float2*)&C[(((size_t)b0v * H_ + h) * S_ + s0) * DK_ + dk] = v0;
                *(float2*)&C[(((size_t)b1v * H_ + h) * S_ + s1) * DK_ + dk] = v1;
            } else {
                *(float2*)&C[(size_t)m0 * D_ + n] = v0;
                *(float2*)&C[(size_t)m1 * D_ + n] = v1;
            }
        }
    }
}

// ---------------------------------------------------------------------------
// K2: raw causal scores  S = Q @ K^T * scale  per (b,h)  (fp32 FFMA)
// ---------------------------------------------------------------------------
__global__ void __launch_bounds__(256)
scores_kernel(const float* __restrict__ Qm, const float* __restrict__ Km,
              float* __restrict__ attn, float scale)
{
    const int BM = 128, BN = 128, BK = 16;
    const int bm = blockIdx.y, bn = blockIdx.x, z = blockIdx.z;
    if (bn * BN > bm * BM + (BM - 1)) return;

    const float* A = Qm + (size_t)z * S_ * DK_;
    const float* W = Km + (size_t)z * S_ * DK_;
    float*       C = attn + (size_t)z * S_ * S_;

    __shared__ float As[BK][BM];
    __shared__ float Ws[BK][BN];

    const int tid = threadIdx.x;
    const int tx = tid & 15, ty = tid >> 4;

    float acc[8][8];
#pragma unroll
    for (int i = 0; i < 8; i++)
#pragma unroll
        for (int j = 0; j < 8; j++) acc[i][j] = 0.0f;

    const int a0 = bm * BM;
    const int w0 = bn * BN;

    for (int k0 = 0; k0 < DK_; k0 += BK) {
#pragma unroll
        for (int l = 0; l < 2; l++) {
            int id  = tid + l * 256;
            int row = id >> 2;
            int kc  = (id & 3) * 4;
            float4 va = *(const float4*)(A + (size_t)(a0 + row) * DK_ + k0 + kc);
            As[kc + 0][row] = va.x; As[kc + 1][row] = va.y;
            As[kc + 2][row] = va.z; As[kc + 3][row] = va.w;
            float4 vw = *(const float4*)(W + (size_t)(w0 + row) * DK_ + k0 + kc);
            Ws[kc + 0][row] = vw.x; Ws[kc + 1][row] = vw.y;
            Ws[kc + 2][row] = vw.z; Ws[kc + 3][row] = vw.w;
        }
        __syncthreads();

#pragma unroll
        for (int k = 0; k < BK; k++) {
            float a[8], b[8];
#pragma unroll
            for (int i = 0; i < 8; i++) a[i] = As[k][ty * 8 + i];
#pragma unroll
            for (int j = 0; j < 8; j++) b[j] = Ws[k][tx * 8 + j];
#pragma unroll
            for (int i = 0; i < 8; i++)
#pragma unroll
                for (int j = 0; j < 8; j++) acc[i][j] += a[i] * b[j];
        }
        __syncthreads();
    }

#pragma unroll
    for (int i = 0; i < 8; i++) {
        int m = a0 + ty * 8 + i;
#pragma unroll
        for (int j = 0; j < 8; j++) {
            int n = w0 + tx * 8 + j;
            C[(size_t)m * S_ + n] = acc[i][j] * scale;
        }
    }
}

// ---------------------------------------------------------------------------
// K3: causal softmax (in place, zero-fills masked region)
// ---------------------------------------------------------------------------
__global__ void __launch_bounds__(256)
softmax_kernel(float* __restrict__ attn)
{
    const int r   = blockIdx.x;
    const int z   = r / S_;
    const int q   = r % S_;
    float* row = attn + (size_t)z * S_ * S_ + (size_t)q * S_;
    const int len = q + 1;
    const int tid = threadIdx.x;
    const int lane = tid & 31, wid = tid >> 5;

    __shared__ float smax[8];
    __shared__ float ssum[8];

    float m = -3.0e38f;
    for (int i = tid; i < len; i += 256) m = fmaxf(m, row[i]);
#pragma unroll
    for (int o = 16; o > 0; o >>= 1) m = fmaxf(m, __shfl_xor_sync(0xffffffffu, m, o));
    if (lane == 0) smax[wid] = m;
    __syncthreads();
    float bmax = smax[0];
#pragma unroll
    for (int w = 1; w < 8; w++) bmax = fmaxf(bmax, smax[w]);

    float s = 0.0f;
    for (int i = tid; i < len; i += 256) s += expf(row[i] - bmax);
#pragma unroll
    for (int o = 16; o > 0; o >>= 1) s += __shfl_xor_sync(0xffffffffu, s, o);
    if (lane == 0) ssum[wid] = s;
    __syncthreads();
    float bsum = 0.0f;
#pragma unroll
    for (int w = 0; w < 8; w++) bsum += ssum[w];
    const float inv = 1.0f / bsum;

    for (int i = tid; i < len; i += 256) row[i] = expf(row[i] - bmax) * inv;
    for (int i = len + tid; i < S_; i += 256) row[i] = 0.0f;
}

// ---------------------------------------------------------------------------
// K4: X = attn @ V per (b,h), k-loop truncated at diagonal (fp32)
// ---------------------------------------------------------------------------
__global__ void __launch_bounds__(256)
pv_kernel(const float* __restrict__ attn, const float* __restrict__ Vm,
          float* __restrict__ Xbsd)
{
    const int BM = 128, BK = 16;
    const int bm = blockIdx.y, z = blockIdx.z;
    const int b = z / H_, h = z % H_;
    const float* A = attn + (size_t)z * S_ * S_;
    const float* V = Vm   + (size_t)z * S_ * DK_;

    __shared__ float As[BK][BM];
    __shared__ float Bs[BK][DK_];

    const int tid = threadIdx.x;
    const int tx = tid & 15, ty = tid >> 4;

    float acc[8][8];
#pragma unroll
    for (int i = 0; i < 8; i++)
#pragma unroll
        for (int j = 0; j < 8; j++) acc[i][j] = 0.0f;

    const int a0 = bm * BM;
    const int kend = (bm + 1) * BM;

    for (int k0 = 0; k0 < kend; k0 += BK) {
#pragma unroll
        for (int l = 0; l < 2; l++) {
            int id  = tid + l * 256;
            int row = id >> 2;
            int kc  = (id & 3) * 4;
            float4 va = *(const float4*)(A + (size_t)(a0 + row) * S_ + k0 + kc);
            As[kc + 0][row] = va.x; As[kc + 1][row] = va.y;
            As[kc + 2][row] = va.z; As[kc + 3][row] = va.w;

            int kr = id >> 5;
            int nc = (id & 31) * 4;
            *(float4*)&Bs[kr][nc] = *(const float4*)(V + (size_t)(k0 + kr) * DK_ + nc);
        }
        __syncthreads();

#pragma unroll
        for (int k = 0; k < BK; k++) {
            float a[8], b8[8];
#pragma unroll
            for (int i = 0; i < 8; i++) a[i] = As[k][ty * 8 + i];
#pragma unroll
            for (int j = 0; j < 8; j++) b8[j] = Bs[k][tx * 8 + j];
#pragma unroll
            for (int i = 0; i < 8; i++)
#pragma unroll
                for (int j = 0; j < 8; j++) acc[i][j] += a[i] * b8[j];
        }
        __syncthreads();
    }

#pragma unroll
    for (int i = 0; i < 8; i++) {
        int s = a0 + ty * 8 + i;
#pragma unroll
        for (int j = 0; j < 8; j++) {
            int dk = tx * 8 + j;
            Xbsd[((size_t)b * S_ + s) * D_ + h * DK_ + dk] = acc[i][j];
        }
    }
}

// ---------------------------------------------------------------------------
// Launch
// ---------------------------------------------------------------------------
extern "C" void kernel_launch(void* const* d_in, const int* in_sizes, int n_in,
                              void* d_out, int out_size)
{
    const float* query = (const float*)d_in[0];
    const float* key   = (const float*)d_in[1];
    const float* value = (const float*)d_in[2];
    const float* Wq    = (const float*)d_in[3];
    const float* bq    = (const float*)d_in[4];
    const float* Wk    = (const float*)d_in[5];
    const float* bk    = (const float*)d_in[6];
    const float* Wv    = (const float*)d_in[7];
    const float* bv    = (const float*)d_in[8];
    const float* Wo    = (const float*)d_in[9];
    const float* bo    = (const float*)d_in[10];
    float* out = (float*)d_out;

    float *pq, *pk, *pv, *px, *pfb;
    cudaGetSymbolAddress((void**)&pq,  g_q);
    cudaGetSymbolAddress((void**)&pk,  g_k);
    cudaGetSymbolAddress((void**)&pv,  g_v);
    cudaGetSymbolAddress((void**)&px,  g_x);
    cudaGetSymbolAddress((void**)&pfb, g_attn_fb);

    __nv_bfloat16 *qi_h, *qi_l, *ki_h, *ki_l, *vi_h, *vi_l, *x_h, *x_l;
    __nv_bfloat16 *wq_h, *wq_l, *wk_h, *wk_l, *wv_h, *wv_l, *wo_h, *wo_l;
    cudaGetSymbolAddress((void**)&qi_h, g_qi_h); cudaGetSymbolAddress((void**)&qi_l, g_qi_l);
    cudaGetSymbolAddress((void**)&ki_h, g_ki_h); cudaGetSymbolAddress((void**)&ki_l, g_ki_l);
    cudaGetSymbolAddress((void**)&vi_h, g_vi_h); cudaGetSymbolAddress((void**)&vi_l, g_vi_l);
    cudaGetSymbolAddress((void**)&x_h,  g_x_h);  cudaGetSymbolAddress((void**)&x_l,  g_x_l);
    cudaGetSymbolAddress((void**)&wq_h, g_wq_h); cudaGetSymbolAddress((void**)&wq_l, g_wq_l);
    cudaGetSymbolAddress((void**)&wk_h, g_wk_h); cudaGetSymbolAddress((void**)&wk_l, g_wk_l);
    cudaGetSymbolAddress((void**)&wv_h, g_wv_h); cudaGetSymbolAddress((void**)&wv_l, g_wv_l);
    cudaGetSymbolAddress((void**)&wo_h, g_wo_h); cudaGetSymbolAddress((void**)&wo_l, g_wo_l);

    float* attn = ((size_t)out_size >= OUT_N + ATTN_N) ? (out + OUT_N) : pfb;

    dim3 blk(256);
    const int IN4 = (M_ * D_) / 4;
    const int WN4 = (D_ * D_) / 4;

    // 0) split fp32 -> bf16 hi/lo
    split_kernel<<<2048, blk>>>(query, qi_h, qi_l, IN4);
    split_kernel<<<2048, blk>>>(key,   ki_h, ki_l, IN4);
    split_kernel<<<2048, blk>>>(value, vi_h, vi_l, IN4);
    split_kernel<<<2048, blk>>>(Wq, wq_h, wq_l, WN4);
    split_kernel<<<2048, blk>>>(Wk, wk_h, wk_l, WN4);
    split_kernel<<<2048, blk>>>(Wv, wv_h, wv_l, WN4);
    split_kernel<<<2048, blk>>>(Wo, wo_h, wo_l, WN4);

    // 1) Q/K/V projections (mma.sync bf16 split) -> [B,H,S,DK] fp32
    dim3 gproj(D_ / BNT, M_ / BMT);             // (16, 32)
    gemm_mma<<<gproj, blk>>>(qi_h, qi_l, wq_h, wq_l, bq, pq, 1);
    gemm_mma<<<gproj, blk>>>(ki_h, ki_l, wk_h, wk_l, bk, pk, 1);
    gemm_mma<<<gproj, blk>>>(vi_h, vi_l, wv_h, wv_l, bv, pv, 1);

    // 2) raw causal scores
    const float scale = 1.0f / sqrtf((float)DK_);
    dim3 gsc(S_ / 128, S_ / 128, B_ * H_);
    scores_kernel<<<gsc, blk>>>(pq, pk, attn, scale);

    // 3) causal softmax in place
    softmax_kernel<<<B_ * H_ * S_, blk>>>(attn);

    // 4) X = attn @ V -> [B,S,D]
    dim3 gpv(1, S_ / 128, B_ * H_);
    pv_kernel<<<gpv, blk>>>(attn, pv, px);

    // 5) split X, then out = X @ Wo^T + bo (mma.sync)
    split_kernel<<<2048, blk>>>(px, x_h, x_l, IN4);
    gemm_mma<<<gproj, blk>>>(x_h, x_l, wo_h, wo_l, bo, out, 0);
}

// round 11
// speedup vs baseline: 2.1443x; 1.3779x over previous
#include <cuda_runtime.h>
#include <cuda_bf16.h>
#include <math.h>
#include <stdint.h>

// Problem constants (B=2, S=2048, D=2048, H=16, DK=128)
#define B_  2
#define S_  2048
#define D_  2048
#define H_  16
#define DK_ 128
#define M_  (B_ * S_)

static const size_t OUT_N  = (size_t)B_ * S_ * D_;        // 8388608
static const size_t ATTN_N = (size_t)B_ * H_ * S_ * S_;   // 134217728
#define BHSDK (B_ * H_ * S_ * DK_)                        // 8388608

// ---------------------------------------------------------------------------
// Scratch (__device__ globals; allocation-free contract)
// ---------------------------------------------------------------------------
__device__ float g_x[B_ * S_ * D_];                       // attn out [B,S,D]
__device__ float g_attn_fb[(size_t)B_ * H_ * S_ * S_];    // fallback scores

// bf16 split operands
__device__ __nv_bfloat16 g_qi_h[M_ * D_], g_qi_l[M_ * D_];   // input splits
__device__ __nv_bfloat16 g_ki_h[M_ * D_], g_ki_l[M_ * D_];
__device__ __nv_bfloat16 g_vi_h[M_ * D_], g_vi_l[M_ * D_];
__device__ __nv_bfloat16 g_x_h [M_ * D_], g_x_l [M_ * D_];
__device__ __nv_bfloat16 g_wq_h[D_ * D_], g_wq_l[D_ * D_];   // weight splits
__device__ __nv_bfloat16 g_wk_h[D_ * D_], g_wk_l[D_ * D_];
__device__ __nv_bfloat16 g_wv_h[D_ * D_], g_wv_l[D_ * D_];
__device__ __nv_bfloat16 g_wo_h[D_ * D_], g_wo_l[D_ * D_];
// projection outputs, bf16 split
__device__ __nv_bfloat16 g_qh[BHSDK], g_ql[BHSDK];           // [B,H,S,DK]
__device__ __nv_bfloat16 g_kh[BHSDK], g_kl[BHSDK];           // [B,H,S,DK]
__device__ __nv_bfloat16 g_vth[BHSDK], g_vtl[BHSDK];         // [B,H,DK,S]

// ---------------------------------------------------------------------------
// Baseline-ISA helpers (sm_80-level: cp.async / ldmatrix / mma.sync only)
// ---------------------------------------------------------------------------
__device__ __forceinline__ uint32_t smem_u32(const void* p) {
    uint32_t a;
    asm("{ .reg .u64 t; cvta.to.shared.u64 t, %1; cvt.u32.u64 %0, t; }"
        : "=r"(a) : "l"(p));
    return a;
}
__device__ __forceinline__ void cpa16(uint32_t saddr, const void* g) {
    asm volatile("cp.async.cg.shared.global [%0], [%1], 16;"
                 :: "r"(saddr), "l"(g));
}
#define CP_COMMIT() asm volatile("cp.async.commit_group;" ::: "memory")
#define CP_WAIT1()  asm volatile("cp.async.wait_group 1;" ::: "memory")
#define CP_WAIT0()  asm volatile("cp.async.wait_group 0;" ::: "memory")

__device__ __forceinline__ void ldmx4(uint32_t& r0, uint32_t& r1,
                                      uint32_t& r2, uint32_t& r3, uint32_t addr) {
    asm volatile("ldmatrix.sync.aligned.m8n8.x4.shared.b16 {%0,%1,%2,%3}, [%4];"
                 : "=r"(r0), "=r"(r1), "=r"(r2), "=r"(r3) : "r"(addr));
}
__device__ __forceinline__ void mma16816(float* c, uint32_t a0, uint32_t a1,
                                         uint32_t a2, uint32_t a3,
                                         uint32_t b0, uint32_t b1) {
    asm volatile(
        "mma.sync.aligned.m16n8k16.row.col.f32.bf16.bf16.f32 "
        "{%0,%1,%2,%3}, {%4,%5,%6,%7}, {%8,%9}, {%0,%1,%2,%3};"
        : "+f"(c[0]), "+f"(c[1]), "+f"(c[2]), "+f"(c[3])
        : "r"(a0), "r"(a1), "r"(a2), "r"(a3), "r"(b0), "r"(b1));
}

// Shared-stage layout: Ah | Al | Bh | Bl, each 128 rows x 32 bf16, PADK pad
#define PADK    40
#define SOFF_AH 0
#define SOFF_AL 10240
#define SOFF_BH 20480
#define SOFF_BL 30720
#define STG     40960
#define DYN_SMEM (2 * STG)   // 80KB

// 3-MMA fused compute on one stage: acc += Ah*Bh + Ah*Bl + Al*Bh
__device__ __forceinline__ void mma_stage(uint32_t sbase, float acc[4][4][4],
                                          int wm, int wn, int lane)
{
    uint32_t bh[4][4], bl[4][4];
#pragma unroll
    for (int ni = 0; ni < 4; ++ni) {
        uint32_t off = ((wn * 32 + ni * 8 + (lane & 7)) * PADK + (lane >> 3) * 8) * 2;
        ldmx4(bh[ni][0], bh[ni][1], bh[ni][2], bh[ni][3], sbase + SOFF_BH + off);
        ldmx4(bl[ni][0], bl[ni][1], bl[ni][2], bl[ni][3], sbase + SOFF_BL + off);
    }
#pragma unroll
    for (int k16 = 0; k16 < 2; ++k16) {
#pragma unroll
        for (int mi = 0; mi < 4; ++mi) {
            uint32_t off = ((wm * 64 + mi * 16 + (lane & 15)) * PADK
                            + (lane >> 4) * 8 + k16 * 16) * 2;
            uint32_t ah0, ah1, ah2, ah3, al0, al1, al2, al3;
            ldmx4(ah0, ah1, ah2, ah3, sbase + SOFF_AH + off);
            ldmx4(al0, al1, al2, al3, sbase + SOFF_AL + off);
#pragma unroll
            for (int ni = 0; ni < 4; ++ni) {
                mma16816(acc[mi][ni], ah0, ah1, ah2, ah3,
                         bh[ni][k16 * 2], bh[ni][k16 * 2 + 1]);
                mma16816(acc[mi][ni], ah0, ah1, ah2, ah3,
                         bl[ni][k16 * 2], bl[ni][k16 * 2 + 1]);
                mma16816(acc[mi][ni], al0, al1, al2, al3,
                         bh[ni][k16 * 2], bh[ni][k16 * 2 + 1]);
            }
        }
    }
}

// ---------------------------------------------------------------------------
// K0: fp32 -> (bf16 hi, bf16 lo) split, vectorized
// ---------------------------------------------------------------------------
__global__ void __launch_bounds__(256)
split_kernel(const float* __restrict__ x, __nv_bfloat16* __restrict__ hi,
             __nv_bfloat16* __restrict__ lo, int n4)
{
    int i = blockIdx.x * 256 + threadIdx.x;
    int stride = gridDim.x * 256;
    for (; i < n4; i += stride) {
        float4 v = ((const float4*)x)[i];
        __nv_bfloat16 h0 = __float2bfloat16(v.x);
        __nv_bfloat16 h1 = __float2bfloat16(v.y);
        __nv_bfloat16 h2 = __float2bfloat16(v.z);
        __nv_bfloat16 h3 = __float2bfloat16(v.w);
        __nv_bfloat16 l0 = __float2bfloat16(v.x - __bfloat162float(h0));
        __nv_bfloat16 l1 = __float2bfloat16(v.y - __bfloat162float(h1));
        __nv_bfloat16 l2 = __float2bfloat16(v.z - __bfloat162float(h2));
        __nv_bfloat16 l3 = __float2bfloat16(v.w - __bfloat162float(h3));
        ((__nv_bfloat162*)hi)[2 * i]     = __nv_bfloat162(h0, h1);
        ((__nv_bfloat162*)hi)[2 * i + 1] = __nv_bfloat162(h2, h3);
        ((__nv_bfloat162*)lo)[2 * i]     = __nv_bfloat162(l0, l1);
        ((__nv_bfloat162*)lo)[2 * i + 1] = __nv_bfloat162(l2, l3);
    }
}

// ---------------------------------------------------------------------------
// K1: projection GEMM  C = A[M,K] @ W[N,K]^T + bias, split fused in k-loop.
// MODE 0: fp32 [M,D]     (O projection)
// MODE 1: bf16 hi/lo -> [B,H,S,DK]   (Q, K)
// MODE 2: bf16 hi/lo -> [B,H,DK,S]   (V, transposed for PV B-operand)
// ---------------------------------------------------------------------------
template <int MODE>
__global__ void __launch_bounds__(256)
gemm_mma(const __nv_bfloat16* __restrict__ Ahi, const __nv_bfloat16* __restrict__ Alo,
         const __nv_bfloat16* __restrict__ Whi, const __nv_bfloat16* __restrict__ Wlo,
         const float* __restrict__ bias, float* __restrict__ Cf,
         __nv_bfloat16* __restrict__ Ch, __nv_bfloat16* __restrict__ Cl)
{
    extern __shared__ char smem[];
    const uint32_t sb = smem_u32(smem);
    const int tid = threadIdx.x, lane = tid & 31, wid = tid >> 5;
    const int wm = wid & 1, wn = wid >> 1;
    const int a0 = blockIdx.y * 128, n0 = blockIdx.x * 128;
    const int row = tid >> 1, sege = (tid & 1) * 16;

    float acc[4][4][4];
#pragma unroll
    for (int i = 0; i < 4; i++)
#pragma unroll
        for (int j = 0; j < 4; j++)
#pragma unroll
            for (int k = 0; k < 4; k++) acc[i][j][k] = 0.0f;

    auto load_stage = [&](int st) {
        const int s = st & 1, k0 = st * 32;
        uint32_t so = sb + s * STG + (row * PADK + sege) * 2;
        const __nv_bfloat16* g;
        g = Ahi + (size_t)(a0 + row) * D_ + k0 + sege;
        cpa16(so + SOFF_AH, g); cpa16(so + SOFF_AH + 16, g + 8);
        g = Alo + (size_t)(a0 + row) * D_ + k0 + sege;
        cpa16(so + SOFF_AL, g); cpa16(so + SOFF_AL + 16, g + 8);
        g = Whi + (size_t)(n0 + row) * D_ + k0 + sege;
        cpa16(so + SOFF_BH, g); cpa16(so + SOFF_BH + 16, g + 8);
        g = Wlo + (size_t)(n0 + row) * D_ + k0 + sege;
        cpa16(so + SOFF_BL, g); cpa16(so + SOFF_BL + 16, g + 8);
    };

    const int NCH = D_ / 32;   // 64
    load_stage(0); CP_COMMIT();
    load_stage(1); CP_COMMIT();
    for (int st = 0; st < NCH; ++st) {
        const int s = st & 1;
        if (st + 1 < NCH) CP_WAIT1(); else CP_WAIT0();
        __syncthreads();
        mma_stage(sb + s * STG, acc, wm, wn, lane);
        __syncthreads();
        if (st + 2 < NCH) { load_stage(st + 2); CP_COMMIT(); }
    }

    // epilogue
#pragma unroll
    for (int mi = 0; mi < 4; ++mi) {
#pragma unroll
        for (int ni = 0; ni < 4; ++ni) {
            const int r = wm * 64 + mi * 16 + (lane >> 2);
            const int c = wn * 32 + ni * 8 + (lane & 3) * 2;
            const int n = n0 + c;
            const int m0 = a0 + r, m1 = m0 + 8;
            float v00 = acc[mi][ni][0] + bias[n];
            float v01 = acc[mi][ni][1] + bias[n + 1];
            float v10 = acc[mi][ni][2] + bias[n];
            float v11 = acc[mi][ni][3] + bias[n + 1];
            if (MODE == 0) {
                *(float2*)&Cf[(size_t)m0 * D_ + n] = make_float2(v00, v01);
                *(float2*)&Cf[(size_t)m1 * D_ + n] = make_float2(v10, v11);
            } else {
                const int h = n >> 7, dk = n & 127;
                const int b0v = m0 >> 11, s0 = m0 & (S_ - 1);
                const int b1v = m1 >> 11, s1 = m1 & (S_ - 1);
                __nv_bfloat16 h00 = __float2bfloat16(v00);
                __nv_bfloat16 h01 = __float2bfloat16(v01);
                __nv_bfloat16 h10 = __float2bfloat16(v10);
                __nv_bfloat16 h11 = __float2bfloat16(v11);
                __nv_bfloat16 l00 = __float2bfloat16(v00 - __bfloat162float(h00));
                __nv_bfloat16 l01 = __float2bfloat16(v01 - __bfloat162float(h01));
                __nv_bfloat16 l10 = __float2bfloat16(v10 - __bfloat162float(h10));
                __nv_bfloat16 l11 = __float2bfloat16(v11 - __bfloat162float(h11));
                if (MODE == 1) {
                    size_t i0 = (((size_t)b0v * H_ + h) * S_ + s0) * DK_ + dk;
                    size_t i1 = (((size_t)b1v * H_ + h) * S_ + s1) * DK_ + dk;
                    *(__nv_bfloat162*)&Ch[i0] = __nv_bfloat162(h00, h01);
                    *(__nv_bfloat162*)&Cl[i0] = __nv_bfloat162(l00, l01);
                    *(__nv_bfloat162*)&Ch[i1] = __nv_bfloat162(h10, h11);
                    *(__nv_bfloat162*)&Cl[i1] = __nv_bfloat162(l10, l11);
                } else {  // MODE 2: transposed [B,H,DK,S]
                    size_t t00 = (((size_t)b0v * H_ + h) * DK_ + dk)     * S_ + s0;
                    size_t t01 = (((size_t)b0v * H_ + h) * DK_ + dk + 1) * S_ + s0;
                    size_t t10 = (((size_t)b1v * H_ + h) * DK_ + dk)     * S_ + s1;
                    size_t t11 = (((size_t)b1v * H_ + h) * DK_ + dk + 1) * S_ + s1;
                    Ch[t00] = h00; Cl[t00] = l00;
                    Ch[t01] = h01; Cl[t01] = l01;
                    Ch[t10] = h10; Cl[t10] = l10;
                    Ch[t11] = h11; Cl[t11] = l11;
                }
            }
        }
    }
}

// ---------------------------------------------------------------------------
// K2: scores via mma.sync — writes exp(score) into attn (masked -> 0)
// ---------------------------------------------------------------------------
__global__ void __launch_bounds__(256)
scores_mma(const __nv_bfloat16* __restrict__ Qh, const __nv_bfloat16* __restrict__ Ql,
           const __nv_bfloat16* __restrict__ Kh, const __nv_bfloat16* __restrict__ Kl,
           float* __restrict__ attn, float scale2)
{
    const int bm = blockIdx.y, bn = blockIdx.x, z = blockIdx.z;
    if (bn > bm) return;
    extern __shared__ char smem[];
    const uint32_t sb = smem_u32(smem);
    const int tid = threadIdx.x, lane = tid & 31, wid = tid >> 5;
    const int wm = wid & 1, wn = wid >> 1;
    const int a0 = bm * 128, n0 = bn * 128;
    const int row = tid >> 1, sege = (tid & 1) * 16;

    const __nv_bfloat16* Qhz = Qh + (size_t)z * S_ * DK_;
    const __nv_bfloat16* Qlz = Ql + (size_t)z * S_ * DK_;
    const __nv_bfloat16* Khz = Kh + (size_t)z * S_ * DK_;
    const __nv_bfloat16* Klz = Kl + (size_t)z * S_ * DK_;
    float* C = attn + (size_t)z * S_ * S_;

    float acc[4][4][4];
#pragma unroll
    for (int i = 0; i < 4; i++)
#pragma unroll
        for (int j = 0; j < 4; j++)
#pragma unroll
            for (int k = 0; k < 4; k++) acc[i][j][k] = 0.0f;

    auto load_stage = [&](int st) {
        const int s = st & 1, k0 = st * 32;
        uint32_t so = sb + s * STG + (row * PADK + sege) * 2;
        const __nv_bfloat16* g;
        g = Qhz + (size_t)(a0 + row) * DK_ + k0 + sege;
        cpa16(so + SOFF_AH, g); cpa16(so + SOFF_AH + 16, g + 8);
        g = Qlz + (size_t)(a0 + row) * DK_ + k0 + sege;
        cpa16(so + SOFF_AL, g); cpa16(so + SOFF_AL + 16, g + 8);
        g = Khz + (size_t)(n0 + row) * DK_ + k0 + sege;
        cpa16(so + SOFF_BH, g); cpa16(so + SOFF_BH + 16, g + 8);
        g = Klz + (size_t)(n0 + row) * DK_ + k0 + sege;
        cpa16(so + SOFF_BL, g); cpa16(so + SOFF_BL + 16, g + 8);
    };

    const int NCH = DK_ / 32;  // 4
    load_stage(0); CP_COMMIT();
    load_stage(1); CP_COMMIT();
    for (int st = 0; st < NCH; ++st) {
        const int s = st & 1;
        if (st + 1 < NCH) CP_WAIT1(); else CP_WAIT0();
        __syncthreads();
        mma_stage(sb + s * STG, acc, wm, wn, lane);
        __syncthreads();
        if (st + 2 < NCH) { load_stage(st + 2); CP_COMMIT(); }
    }

    // epilogue: e = exp2(score * scale2), zero above diagonal
#pragma unroll
    for (int mi = 0; mi < 4; ++mi) {
#pragma unroll
        for (int ni = 0; ni < 4; ++ni) {
            const int r = wm * 64 + mi * 16 + (lane >> 2);
            const int c = wn * 32 + ni * 8 + (lane & 3) * 2;
            const int m0 = a0 + r, m1 = m0 + 8;
            const int n = n0 + c;
            float e00 = (n     <= m0) ? exp2f(acc[mi][ni][0] * scale2) : 0.0f;
            float e01 = (n + 1 <= m0) ? exp2f(acc[mi][ni][1] * scale2) : 0.0f;
            float e10 = (n     <= m1) ? exp2f(acc[mi][ni][2] * scale2) : 0.0f;
            float e11 = (n + 1 <= m1) ? exp2f(acc[mi][ni][3] * scale2) : 0.0f;
            *(float2*)&C[(size_t)m0 * S_ + n] = make_float2(e00, e01);
            *(float2*)&C[(size_t)m1 * S_ + n] = make_float2(e10, e11);
        }
    }
}

// ---------------------------------------------------------------------------
// K3: normalize — per row: sum exp, scale by 1/sum, zero-fill above diagonal
// ---------------------------------------------------------------------------
__global__ void __launch_bounds__(256)
norm_kernel(float* __restrict__ attn)
{
    const int r = blockIdx.x;
    const int z = r >> 11, q = r & (S_ - 1);
    float* row = attn + (size_t)z * S_ * S_ + (size_t)q * S_;
    const int len = q + 1;
    const int tid = threadIdx.x;
    const int lane = tid & 31, wid = tid >> 5;
    __shared__ float ssum[8];

    float s = 0.0f;
    for (int i = tid; i < len; i += 256) s += row[i];
#pragma unroll
    for (int o = 16; o > 0; o >>= 1) s += __shfl_xor_sync(0xffffffffu, s, o);
    if (lane == 0) ssum[wid] = s;
    __syncthreads();
    float bsum = 0.0f;
#pragma unroll
    for (int w = 0; w < 8; w++) bsum += ssum[w];
    const float inv = 1.0f / bsum;

    for (int i = tid; i < len; i += 256) row[i] *= inv;
    for (int i = len + tid; i < S_; i += 256) row[i] = 0.0f;
}

// ---------------------------------------------------------------------------
// K4: PV via mma.sync — A = attn fp32 (split in-kernel), B = V^T bf16 hi/lo
// ---------------------------------------------------------------------------
__global__ void __launch_bounds__(256)
pv_mma(const float* __restrict__ attn,
       const __nv_bfloat16* __restrict__ Vth, const __nv_bfloat16* __restrict__ Vtl,
       float* __restrict__ Xbsd)
{
    const int bm = blockIdx.y, z = blockIdx.z;
    const int b = z / H_, h = z % H_;
    extern __shared__ char smem[];
    const uint32_t sb = smem_u32(smem);
    const int tid = threadIdx.x, lane = tid & 31, wid = tid >> 5;
    const int wm = wid & 1, wn = wid >> 1;
    const int a0 = bm * 128;
    const int row = tid >> 1, sege = (tid & 1) * 16;

    const float* Az = attn + (size_t)z * S_ * S_;
    const __nv_bfloat16* Vh = Vth + (size_t)z * DK_ * S_;
    const __nv_bfloat16* Vl = Vtl + (size_t)z * DK_ * S_;
    const int NCH = (bm + 1) * 4;        // causal truncation

    float acc[4][4][4];
#pragma unroll
    for (int i = 0; i < 4; i++)
#pragma unroll
        for (int j = 0; j < 4; j++)
#pragma unroll
            for (int k = 0; k < 4; k++) acc[i][j][k] = 0.0f;

    float4 pre[4];
    auto loadV = [&](int c, int s) {
        uint32_t so = sb + s * STG + (row * PADK + sege) * 2;
        const __nv_bfloat16* g;
        g = Vh + (size_t)row * S_ + c * 32 + sege;    // row = dk
        cpa16(so + SOFF_BH, g); cpa16(so + SOFF_BH + 16, g + 8);
        g = Vl + (size_t)row * S_ + c * 32 + sege;
        cpa16(so + SOFF_BL, g); cpa16(so + SOFF_BL + 16, g + 8);
    };
    auto loadA = [&](int c) {
        const float* g = Az + (size_t)(a0 + row) * S_ + c * 32 + sege;
#pragma unroll
        for (int j = 0; j < 4; ++j) pre[j] = *(const float4*)(g + j * 4);
    };
    auto storeA = [&](int s) {
        char* p = smem + s * STG + (row * PADK + sege) * 2;
#pragma unroll
        for (int j = 0; j < 4; ++j) {
            float4 v = pre[j];
            __nv_bfloat16 h0 = __float2bfloat16(v.x);
            __nv_bfloat16 h1 = __float2bfloat16(v.y);
            __nv_bfloat16 h2 = __float2bfloat16(v.z);
            __nv_bfloat16 h3 = __float2bfloat16(v.w);
            __nv_bfloat16 l0 = __float2bfloat16(v.x - __bfloat162float(h0));
            __nv_bfloat16 l1 = __float2bfloat16(v.y - __bfloat162float(h1));
            __nv_bfloat16 l2 = __float2bfloat16(v.z - __bfloat162float(h2));
            __nv_bfloat16 l3 = __float2bfloat16(v.w - __bfloat162float(h3));
            *(__nv_bfloat162*)(p + SOFF_AH + j * 8)     = __nv_bfloat162(h0, h1);
            *(__nv_bfloat162*)(p + SOFF_AH + j * 8 + 4) = __nv_bfloat162(h2, h3);
            *(__nv_bfloat162*)(p + SOFF_AL + j * 8)     = __nv_bfloat162(l0, l1);
            *(__nv_bfloat162*)(p + SOFF_AL + j * 8 + 4) = __nv_bfloat162(l2, l3);
        }
    };

    loadV(0, 0); CP_COMMIT();
    loadA(0);
    for (int c = 0; c < NCH; ++c) {
        const int s = c & 1;
        storeA(s);
        if (c + 1 < NCH) { loadV(c + 1, s ^ 1); CP_COMMIT(); CP_WAIT1(); }
        else             { CP_WAIT0(); }
        __syncthreads();
        if (c + 1 < NCH) loadA(c + 1);
        mma_stage(sb + s * STG, acc, wm, wn, lane);
        __syncthreads();
    }

    // epilogue: X[b, q, h*DK + dk]
#pragma unroll
    for (int mi = 0; mi < 4; ++mi) {
#pragma unroll
        for (int ni = 0; ni < 4; ++ni) {
            const int r = wm * 64 + mi * 16 + (lane >> 2);
            const int c = wn * 32 + ni * 8 + (lane & 3) * 2;
            const int m0 = a0 + r, m1 = m0 + 8;
            size_t i0 = ((size_t)b * S_ + m0) * D_ + h * DK_ + c;
            size_t i1 = ((size_t)b * S_ + m1) * D_ + h * DK_ + c;
            *(float2*)&Xbsd[i0] = make_float2(acc[mi][ni][0], acc[mi][ni][1]);
            *(float2*)&Xbsd[i1] = make_float2(acc[mi][ni][2], acc[mi][ni][3]);
        }
    }
}

// ---------------------------------------------------------------------------
// Launch
// ---------------------------------------------------------------------------
extern "C" void kernel_launch(void* const* d_in, const int* in_sizes, int n_in,
                              void* d_out, int out_size)
{
    const float* query = (const float*)d_in[0];
    const float* key   = (const float*)d_in[1];
    const float* value = (const float*)d_in[2];
    const float* Wq    = (const float*)d_in[3];
    const float* bq    = (const float*)d_in[4];
    const float* Wk    = (const float*)d_in[5];
    const float* bk    = (const float*)d_in[6];
    const float* Wv    = (const float*)d_in[7];
    const float* bv    = (const float*)d_in[8];
    const float* Wo    = (const float*)d_in[9];
    const float* bo    = (const float*)d_in[10];
    float* out = (float*)d_out;

    float *px, *pfb;
    cudaGetSymbolAddress((void**)&px,  g_x);
    cudaGetSymbolAddress((void**)&pfb, g_attn_fb);

    __nv_bfloat16 *qi_h, *qi_l, *ki_h, *ki_l, *vi_h, *vi_l, *x_h, *x_l;
    __nv_bfloat16 *wq_h, *wq_l, *wk_h, *wk_l, *wv_h, *wv_l, *wo_h, *wo_l;
    __nv_bfloat16 *qh, *ql, *kh, *kl, *vth, *vtl;
    cudaGetSymbolAddress((void**)&qi_h, g_qi_h); cudaGetSymbolAddress((void**)&qi_l, g_qi_l);
    cudaGetSymbolAddress((void**)&ki_h, g_ki_h); cudaGetSymbolAddress((void**)&ki_l, g_ki_l);
    cudaGetSymbolAddress((void**)&vi_h, g_vi_h); cudaGetSymbolAddress((void**)&vi_l, g_vi_l);
    cudaGetSymbolAddress((void**)&x_h,  g_x_h);  cudaGetSymbolAddress((void**)&x_l,  g_x_l);
    cudaGetSymbolAddress((void**)&wq_h, g_wq_h); cudaGetSymbolAddress((void**)&wq_l, g_wq_l);
    cudaGetSymbolAddress((void**)&wk_h, g_wk_h); cudaGetSymbolAddress((void**)&wk_l, g_wk_l);
    cudaGetSymbolAddress((void**)&wv_h, g_wv_h); cudaGetSymbolAddress((void**)&wv_l, g_wv_l);
    cudaGetSymbolAddress((void**)&wo_h, g_wo_h); cudaGetSymbolAddress((void**)&wo_l, g_wo_l);
    cudaGetSymbolAddress((void**)&qh, g_qh);   cudaGetSymbolAddress((void**)&ql, g_ql);
    cudaGetSymbolAddress((void**)&kh, g_kh);   cudaGetSymbolAddress((void**)&kl, g_kl);
    cudaGetSymbolAddress((void**)&vth, g_vth); cudaGetSymbolAddress((void**)&vtl, g_vtl);

    float* attn = ((size_t)out_size >= OUT_N + ATTN_N) ? (out + OUT_N) : pfb;

    cudaFuncSetAttribute(gemm_mma<0>, cudaFuncAttributeMaxDynamicSharedMemorySize, DYN_SMEM);
    cudaFuncSetAttribute(gemm_mma<1>, cudaFuncAttributeMaxDynamicSharedMemorySize, DYN_SMEM);
    cudaFuncSetAttribute(gemm_mma<2>, cudaFuncAttributeMaxDynamicSharedMemorySize, DYN_SMEM);
    cudaFuncSetAttribute(scores_mma,  cudaFuncAttributeMaxDynamicSharedMemorySize, DYN_SMEM);
    cudaFuncSetAttribute(pv_mma,      cudaFuncAttributeMaxDynamicSharedMemorySize, DYN_SMEM);

    dim3 blk(256);
    const int IN4 = (M_ * D_) / 4;
    const int WN4 = (D_ * D_) / 4;

    // 0) split fp32 -> bf16 hi/lo (inputs + weights)
    split_kernel<<<2048, blk>>>(query, qi_h, qi_l, IN4);
    split_kernel<<<2048, blk>>>(key,   ki_h, ki_l, IN4);
    split_kernel<<<2048, blk>>>(value, vi_h, vi_l, IN4);
    split_kernel<<<2048, blk>>>(Wq, wq_h, wq_l, WN4);
    split_kernel<<<2048, blk>>>(Wk, wk_h, wk_l, WN4);
    split_kernel<<<2048, blk>>>(Wv, wv_h, wv_l, WN4);
    split_kernel<<<2048, blk>>>(Wo, wo_h, wo_l, WN4);

    // 1) projections -> bf16 split Q/K [B,H,S,DK], V^T [B,H,DK,S]
    dim3 gproj(D_ / 128, M_ / 128);   // (16, 32)
    gemm_mma<1><<<gproj, blk, DYN_SMEM>>>(qi_h, qi_l, wq_h, wq_l, bq, nullptr, qh, ql);
    gemm_mma<1><<<gproj, blk, DYN_SMEM>>>(ki_h, ki_l, wk_h, wk_l, bk, nullptr, kh, kl);
    gemm_mma<2><<<gproj, blk, DYN_SMEM>>>(vi_h, vi_l, wv_h, wv_l, bv, nullptr, vth, vtl);

    // 2) scores -> exp(score) in attn buffer (tensor cores, fused exp)
    const float scale2 = (1.0f / sqrtf((float)DK_)) * 1.44269504088896f; // log2(e)
    dim3 gsc(S_ / 128, S_ / 128, B_ * H_);
    scores_mma<<<gsc, blk, DYN_SMEM>>>(qh, ql, kh, kl, attn, scale2);

    // 3) normalize rows (sum + scale + zero-fill)
    norm_kernel<<<B_ * H_ * S_, blk>>>(attn);

    // 4) X = attn @ V (tensor cores, attn split in-kernel)
    dim3 gpv(1, S_ / 128, B_ * H_);
    pv_mma<<<gpv, blk, DYN_SMEM>>>(attn, vth, vtl, px);

    // 5) out = X @ Wo^T + bo
    split_kernel<<<2048, blk>>>(px, x_h, x_l, IN4);
    gemm_mma<0><<<gproj, blk, DYN_SMEM>>>(x_h, x_l, wo_h, wo_l, bo, out, nullptr, nullptr);
}

// round 12
// speedup vs baseline: 2.1889x; 1.0208x over previous
#include <cuda_runtime.h>
#include <cuda_bf16.h>
#include <math.h>
#include <stdint.h>

// Problem constants (B=2, S=2048, D=2048, H=16, DK=128)
#define B_  2
#define S_  2048
#define D_  2048
#define H_  16
#define DK_ 128
#define M_  (B_ * S_)

static const size_t OUT_N  = (size_t)B_ * S_ * D_;        // 8388608
static const size_t ATTN_N = (size_t)B_ * H_ * S_ * S_;   // 134217728
#define BHSDK (B_ * H_ * S_ * DK_)                        // 8388608

// ---------------------------------------------------------------------------
// Scratch (__device__ globals; allocation-free contract)
// ---------------------------------------------------------------------------
__device__ float g_attn_fb[(size_t)B_ * H_ * S_ * S_];    // fallback scores
__device__ float g_psum[(size_t)B_ * H_ * S_ * 16];       // per-tile row partial sums
__device__ float g_rinv[B_ * H_ * S_];                    // 1 / row sum

// bf16 split operands
__device__ __nv_bfloat16 g_qi_h[M_ * D_], g_qi_l[M_ * D_];   // input splits
__device__ __nv_bfloat16 g_ki_h[M_ * D_], g_ki_l[M_ * D_];
__device__ __nv_bfloat16 g_vi_h[M_ * D_], g_vi_l[M_ * D_];
__device__ __nv_bfloat16 g_x_h [M_ * D_], g_x_l [M_ * D_];   // X (PV out) splits
__device__ __nv_bfloat16 g_wq_h[D_ * D_], g_wq_l[D_ * D_];   // weight splits
__device__ __nv_bfloat16 g_wk_h[D_ * D_], g_wk_l[D_ * D_];
__device__ __nv_bfloat16 g_wv_h[D_ * D_], g_wv_l[D_ * D_];
__device__ __nv_bfloat16 g_wo_h[D_ * D_], g_wo_l[D_ * D_];
// projection outputs, bf16 split
__device__ __nv_bfloat16 g_qh[BHSDK], g_ql[BHSDK];           // [B,H,S,DK]
__device__ __nv_bfloat16 g_kh[BHSDK], g_kl[BHSDK];           // [B,H,S,DK]
__device__ __nv_bfloat16 g_vth[BHSDK], g_vtl[BHSDK];         // [B,H,DK,S]

// ---------------------------------------------------------------------------
// Baseline-ISA helpers (sm_80-level: cp.async / ldmatrix / mma.sync only)
// ---------------------------------------------------------------------------
__device__ __forceinline__ uint32_t smem_u32(const void* p) {
    uint32_t a;
    asm("{ .reg .u64 t; cvta.to.shared.u64 t, %1; cvt.u32.u64 %0, t; }"
        : "=r"(a) : "l"(p));
    return a;
}
__device__ __forceinline__ void cpa16(uint32_t saddr, const void* g) {
    asm volatile("cp.async.cg.shared.global [%0], [%1], 16;"
                 :: "r"(saddr), "l"(g));
}
#define CP_COMMIT() asm volatile("cp.async.commit_group;" ::: "memory")
#define CP_WAIT1()  asm volatile("cp.async.wait_group 1;" ::: "memory")
#define CP_WAIT0()  asm volatile("cp.async.wait_group 0;" ::: "memory")

__device__ __forceinline__ void ldmx4(uint32_t& r0, uint32_t& r1,
                                      uint32_t& r2, uint32_t& r3, uint32_t addr) {
    asm volatile("ldmatrix.sync.aligned.m8n8.x4.shared.b16 {%0,%1,%2,%3}, [%4];"
                 : "=r"(r0), "=r"(r1), "=r"(r2), "=r"(r3) : "r"(addr));
}
__device__ __forceinline__ void mma16816(float* c, uint32_t a0, uint32_t a1,
                                         uint32_t a2, uint32_t a3,
                                         uint32_t b0, uint32_t b1) {
    asm volatile(
        "mma.sync.aligned.m16n8k16.row.col.f32.bf16.bf16.f32 "
        "{%0,%1,%2,%3}, {%4,%5,%6,%7}, {%8,%9}, {%0,%1,%2,%3};"
        : "+f"(c[0]), "+f"(c[1]), "+f"(c[2]), "+f"(c[3])
        : "r"(a0), "r"(a1), "r"(a2), "r"(a3), "r"(b0), "r"(b1));
}

// Shared-stage layout: Ah | Al | Bh | Bl, each 128 rows x 32 bf16, PADK pad
#define PADK    40
#define SOFF_AH 0
#define SOFF_AL 10240
#define SOFF_BH 20480
#define SOFF_BL 30720
#define STG     40960
#define DYN_SMEM (2 * STG)   // 80KB

// 3-MMA fused compute on one stage: acc += Ah*Bh + Ah*Bl + Al*Bh
__device__ __forceinline__ void mma_stage(uint32_t sbase, float acc[4][4][4],
                                          int wm, int wn, int lane)
{
    uint32_t bh[4][4], bl[4][4];
#pragma unroll
    for (int ni = 0; ni < 4; ++ni) {
        uint32_t off = ((wn * 32 + ni * 8 + (lane & 7)) * PADK + (lane >> 3) * 8) * 2;
        ldmx4(bh[ni][0], bh[ni][1], bh[ni][2], bh[ni][3], sbase + SOFF_BH + off);
        ldmx4(bl[ni][0], bl[ni][1], bl[ni][2], bl[ni][3], sbase + SOFF_BL + off);
    }
#pragma unroll
    for (int k16 = 0; k16 < 2; ++k16) {
#pragma unroll
        for (int mi = 0; mi < 4; ++mi) {
            uint32_t off = ((wm * 64 + mi * 16 + (lane & 15)) * PADK
                            + (lane >> 4) * 8 + k16 * 16) * 2;
            uint32_t ah0, ah1, ah2, ah3, al0, al1, al2, al3;
            ldmx4(ah0, ah1, ah2, ah3, sbase + SOFF_AH + off);
            ldmx4(al0, al1, al2, al3, sbase + SOFF_AL + off);
#pragma unroll
            for (int ni = 0; ni < 4; ++ni) {
                mma16816(acc[mi][ni], ah0, ah1, ah2, ah3,
                         bh[ni][k16 * 2], bh[ni][k16 * 2 + 1]);
                mma16816(acc[mi][ni], ah0, ah1, ah2, ah3,
                         bl[ni][k16 * 2], bl[ni][k16 * 2 + 1]);
                mma16816(acc[mi][ni], al0, al1, al2, al3,
                         bh[ni][k16 * 2], bh[ni][k16 * 2 + 1]);
            }
        }
    }
}

// ---------------------------------------------------------------------------
// K0: fp32 -> (bf16 hi, bf16 lo) split, vectorized
// ---------------------------------------------------------------------------
__global__ void __launch_bounds__(256)
split_kernel(const float* __restrict__ x, __nv_bfloat16* __restrict__ hi,
             __nv_bfloat16* __restrict__ lo, int n4)
{
    int i = blockIdx.x * 256 + threadIdx.x;
    int stride = gridDim.x * 256;
    for (; i < n4; i += stride) {
        float4 v = ((const float4*)x)[i];
        __nv_bfloat16 h0 = __float2bfloat16(v.x);
        __nv_bfloat16 h1 = __float2bfloat16(v.y);
        __nv_bfloat16 h2 = __float2bfloat16(v.z);
        __nv_bfloat16 h3 = __float2bfloat16(v.w);
        __nv_bfloat16 l0 = __float2bfloat16(v.x - __bfloat162float(h0));
        __nv_bfloat16 l1 = __float2bfloat16(v.y - __bfloat162float(h1));
        __nv_bfloat16 l2 = __float2bfloat16(v.z - __bfloat162float(h2));
        __nv_bfloat16 l3 = __float2bfloat16(v.w - __bfloat162float(h3));
        ((__nv_bfloat162*)hi)[2 * i]     = __nv_bfloat162(h0, h1);
        ((__nv_bfloat162*)hi)[2 * i + 1] = __nv_bfloat162(h2, h3);
        ((__nv_bfloat162*)lo)[2 * i]     = __nv_bfloat162(l0, l1);
        ((__nv_bfloat162*)lo)[2 * i + 1] = __nv_bfloat162(l2, l3);
    }
}

// ---------------------------------------------------------------------------
// K1: projection GEMM  C = A[M,K] @ W[N,K]^T + bias, split fused in k-loop.
// MODE 0: fp32 n/a, bf16 hi/lo [M,D]  (O projection writes fp32 to Cf)
// MODE 1: bf16 hi/lo -> [B,H,S,DK]   (Q, K)
// MODE 2: bf16 hi/lo -> [B,H,DK,S]   (V, transposed for PV B-operand)
// ---------------------------------------------------------------------------
template <int MODE>
__global__ void __launch_bounds__(256)
gemm_mma(const __nv_bfloat16* __restrict__ Ahi, const __nv_bfloat16* __restrict__ Alo,
         const __nv_bfloat16* __restrict__ Whi, const __nv_bfloat16* __restrict__ Wlo,
         const float* __restrict__ bias, float* __restrict__ Cf,
         __nv_bfloat16* __restrict__ Ch, __nv_bfloat16* __restrict__ Cl)
{
    extern __shared__ char smem[];
    const uint32_t sb = smem_u32(smem);
    const int tid = threadIdx.x, lane = tid & 31, wid = tid >> 5;
    const int wm = wid & 1, wn = wid >> 1;
    const int a0 = blockIdx.y * 128, n0 = blockIdx.x * 128;
    const int row = tid >> 1, sege = (tid & 1) * 16;

    float acc[4][4][4];
#pragma unroll
    for (int i = 0; i < 4; i++)
#pragma unroll
        for (int j = 0; j < 4; j++)
#pragma unroll
            for (int k = 0; k < 4; k++) acc[i][j][k] = 0.0f;

    auto load_stage = [&](int st) {
        const int s = st & 1, k0 = st * 32;
        uint32_t so = sb + s * STG + (row * PADK + sege) * 2;
        const __nv_bfloat16* g;
        g = Ahi + (size_t)(a0 + row) * D_ + k0 + sege;
        cpa16(so + SOFF_AH, g); cpa16(so + SOFF_AH + 16, g + 8);
        g = Alo + (size_t)(a0 + row) * D_ + k0 + sege;
        cpa16(so + SOFF_AL, g); cpa16(so + SOFF_AL + 16, g + 8);
        g = Whi + (size_t)(n0 + row) * D_ + k0 + sege;
        cpa16(so + SOFF_BH, g); cpa16(so + SOFF_BH + 16, g + 8);
        g = Wlo + (size_t)(n0 + row) * D_ + k0 + sege;
        cpa16(so + SOFF_BL, g); cpa16(so + SOFF_BL + 16, g + 8);
    };

    const int NCH = D_ / 32;   // 64
    load_stage(0); CP_COMMIT();
    load_stage(1); CP_COMMIT();
    for (int st = 0; st < NCH; ++st) {
        const int s = st & 1;
        if (st + 1 < NCH) CP_WAIT1(); else CP_WAIT0();
        __syncthreads();
        mma_stage(sb + s * STG, acc, wm, wn, lane);
        __syncthreads();
        if (st + 2 < NCH) { load_stage(st + 2); CP_COMMIT(); }
    }

    // epilogue
#pragma unroll
    for (int mi = 0; mi < 4; ++mi) {
#pragma unroll
        for (int ni = 0; ni < 4; ++ni) {
            const int r = wm * 64 + mi * 16 + (lane >> 2);
            const int c = wn * 32 + ni * 8 + (lane & 3) * 2;
            const int n = n0 + c;
            const int m0 = a0 + r, m1 = m0 + 8;
            float v00 = acc[mi][ni][0] + bias[n];
            float v01 = acc[mi][ni][1] + bias[n + 1];
            float v10 = acc[mi][ni][2] + bias[n];
            float v11 = acc[mi][ni][3] + bias[n + 1];
            if (MODE == 0) {
                *(float2*)&Cf[(size_t)m0 * D_ + n] = make_float2(v00, v01);
                *(float2*)&Cf[(size_t)m1 * D_ + n] = make_float2(v10, v11);
            } else {
                const int h = n >> 7, dk = n & 127;
                const int b0v = m0 >> 11, s0 = m0 & (S_ - 1);
                const int b1v = m1 >> 11, s1 = m1 & (S_ - 1);
                __nv_bfloat16 h00 = __float2bfloat16(v00);
                __nv_bfloat16 h01 = __float2bfloat16(v01);
                __nv_bfloat16 h10 = __float2bfloat16(v10);
                __nv_bfloat16 h11 = __float2bfloat16(v11);
                __nv_bfloat16 l00 = __float2bfloat16(v00 - __bfloat162float(h00));
                __nv_bfloat16 l01 = __float2bfloat16(v01 - __bfloat162float(h01));
                __nv_bfloat16 l10 = __float2bfloat16(v10 - __bfloat162float(h10));
                __nv_bfloat16 l11 = __float2bfloat16(v11 - __bfloat162float(h11));
                if (MODE == 1) {
                    size_t i0 = (((size_t)b0v * H_ + h) * S_ + s0) * DK_ + dk;
                    size_t i1 = (((size_t)b1v * H_ + h) * S_ + s1) * DK_ + dk;
                    *(__nv_bfloat162*)&Ch[i0] = __nv_bfloat162(h00, h01);
                    *(__nv_bfloat162*)&Cl[i0] = __nv_bfloat162(l00, l01);
                    *(__nv_bfloat162*)&Ch[i1] = __nv_bfloat162(h10, h11);
                    *(__nv_bfloat162*)&Cl[i1] = __nv_bfloat162(l10, l11);
                } else {  // MODE 2: transposed [B,H,DK,S]
                    size_t t00 = (((size_t)b0v * H_ + h) * DK_ + dk)     * S_ + s0;
                    size_t t01 = (((size_t)b0v * H_ + h) * DK_ + dk + 1) * S_ + s0;
                    size_t t10 = (((size_t)b1v * H_ + h) * DK_ + dk)     * S_ + s1;
                    size_t t11 = (((size_t)b1v * H_ + h) * DK_ + dk + 1) * S_ + s1;
                    Ch[t00] = h00; Cl[t00] = l00;
                    Ch[t01] = h01; Cl[t01] = l01;
                    Ch[t10] = h10; Cl[t10] = l10;
                    Ch[t11] = h11; Cl[t11] = l11;
                }
            }
        }
    }
}

// ---------------------------------------------------------------------------
// K2: scores via mma.sync — writes exp(score) into attn (masked -> 0) and
// deterministic per-tile row partial sums into g_psum[z*S+row][bn].
// ---------------------------------------------------------------------------
__global__ void __launch_bounds__(256)
scores_mma(const __nv_bfloat16* __restrict__ Qh, const __nv_bfloat16* __restrict__ Ql,
           const __nv_bfloat16* __restrict__ Kh, const __nv_bfloat16* __restrict__ Kl,
           float* __restrict__ attn, float* __restrict__ psum, float scale2)
{
    const int bm = blockIdx.y, bn = blockIdx.x, z = blockIdx.z;
    if (bn > bm) return;
    extern __shared__ char smem[];
    __shared__ float sps[4][128];
    const uint32_t sb = smem_u32(smem);
    const int tid = threadIdx.x, lane = tid & 31, wid = tid >> 5;
    const int wm = wid & 1, wn = wid >> 1;
    const int a0 = bm * 128, n0 = bn * 128;
    const int row = tid >> 1, sege = (tid & 1) * 16;

    const __nv_bfloat16* Qhz = Qh + (size_t)z * S_ * DK_;
    const __nv_bfloat16* Qlz = Ql + (size_t)z * S_ * DK_;
    const __nv_bfloat16* Khz = Kh + (size_t)z * S_ * DK_;
    const __nv_bfloat16* Klz = Kl + (size_t)z * S_ * DK_;
    float* C = attn + (size_t)z * S_ * S_;

    float acc[4][4][4];
#pragma unroll
    for (int i = 0; i < 4; i++)
#pragma unroll
        for (int j = 0; j < 4; j++)
#pragma unroll
            for (int k = 0; k < 4; k++) acc[i][j][k] = 0.0f;

    auto load_stage = [&](int st) {
        const int s = st & 1, k0 = st * 32;
        uint32_t so = sb + s * STG + (row * PADK + sege) * 2;
        const __nv_bfloat16* g;
        g = Qhz + (size_t)(a0 + row) * DK_ + k0 + sege;
        cpa16(so + SOFF_AH, g); cpa16(so + SOFF_AH + 16, g + 8);
        g = Qlz + (size_t)(a0 + row) * DK_ + k0 + sege;
        cpa16(so + SOFF_AL, g); cpa16(so + SOFF_AL + 16, g + 8);
        g = Khz + (size_t)(n0 + row) * DK_ + k0 + sege;
        cpa16(so + SOFF_BH, g); cpa16(so + SOFF_BH + 16, g + 8);
        g = Klz + (size_t)(n0 + row) * DK_ + k0 + sege;
        cpa16(so + SOFF_BL, g); cpa16(so + SOFF_BL + 16, g + 8);
    };

    const int NCH = DK_ / 32;  // 4
    load_stage(0); CP_COMMIT();
    load_stage(1); CP_COMMIT();
    for (int st = 0; st < NCH; ++st) {
        const int s = st & 1;
        if (st + 1 < NCH) CP_WAIT1(); else CP_WAIT0();
        __syncthreads();
        mma_stage(sb + s * STG, acc, wm, wn, lane);
        __syncthreads();
        if (st + 2 < NCH) { load_stage(st + 2); CP_COMMIT(); }
    }

    // epilogue: e = exp2(score * scale2), zero above diagonal; row partials
    float rs0[4] = {0, 0, 0, 0}, rs1[4] = {0, 0, 0, 0};
#pragma unroll
    for (int mi = 0; mi < 4; ++mi) {
#pragma unroll
        for (int ni = 0; ni < 4; ++ni) {
            const int r = wm * 64 + mi * 16 + (lane >> 2);
            const int c = wn * 32 + ni * 8 + (lane & 3) * 2;
            const int m0 = a0 + r, m1 = m0 + 8;
            const int n = n0 + c;
            float e00 = (n     <= m0) ? exp2f(acc[mi][ni][0] * scale2) : 0.0f;
            float e01 = (n + 1 <= m0) ? exp2f(acc[mi][ni][1] * scale2) : 0.0f;
            float e10 = (n     <= m1) ? exp2f(acc[mi][ni][2] * scale2) : 0.0f;
            float e11 = (n + 1 <= m1) ? exp2f(acc[mi][ni][3] * scale2) : 0.0f;
            *(float2*)&C[(size_t)m0 * S_ + n] = make_float2(e00, e01);
            *(float2*)&C[(size_t)m1 * S_ + n] = make_float2(e10, e11);
            rs0[mi] += e00 + e01;
            rs1[mi] += e10 + e11;
        }
    }
    // reduce across the 4 lanes sharing a row (lane&3), deterministic order
#pragma unroll
    for (int mi = 0; mi < 4; ++mi) {
        float a = rs0[mi], b = rs1[mi];
        a += __shfl_xor_sync(0xffffffffu, a, 1);
        a += __shfl_xor_sync(0xffffffffu, a, 2);
        b += __shfl_xor_sync(0xffffffffu, b, 1);
        b += __shfl_xor_sync(0xffffffffu, b, 2);
        if ((lane & 3) == 0) {
            int r0 = wm * 64 + mi * 16 + (lane >> 2);
            sps[wn][r0]     = a;
            sps[wn][r0 + 8] = b;
        }
    }
    __syncthreads();
    if (tid < 128) {
        float s = sps[0][tid] + sps[1][tid] + sps[2][tid] + sps[3][tid];
        psum[((size_t)z * S_ + a0 + tid) * 16 + bn] = s;
    }
}

// ---------------------------------------------------------------------------
// K3a: finalize row sums -> 1/sum (deterministic tile-ordered reduction)
// ---------------------------------------------------------------------------
__global__ void __launch_bounds__(256)
sumfin_kernel(const float* __restrict__ psum, float* __restrict__ rinv)
{
    int idx = blockIdx.x * 256 + threadIdx.x;   // z*S + q, 0..65535
    int q = idx & (S_ - 1);
    int nt = (q >> 7) + 1;
    float s = 0.0f;
    for (int i = 0; i < nt; ++i) s += psum[(size_t)idx * 16 + i];
    rinv[idx] = 1.0f / s;
}

// ---------------------------------------------------------------------------
// K3b: zero-fill strictly-upper region of attn (float4)
// ---------------------------------------------------------------------------
__global__ void __launch_bounds__(256)
zero_kernel(float* __restrict__ attn)
{
    const int r = blockIdx.x;
    const int z = r >> 11, q = r & (S_ - 1);
    float* row = attn + (size_t)z * S_ * S_ + (size_t)q * S_;
    const int start = q + 1;
    if (start >= S_) return;
    const int a4 = (start + 3) & ~3;
    const int tid = threadIdx.x;
    if (tid < a4 - start) row[start + tid] = 0.0f;
    const float4 z4 = make_float4(0.f, 0.f, 0.f, 0.f);
    for (int i = (a4 >> 2) + tid; i < (S_ >> 2); i += 256)
        ((float4*)row)[i] = z4;
}

// ---------------------------------------------------------------------------
// K4: PV via mma.sync — reads exp attn, scales by rinv, writes normalized
// attn back in place, computes X = attn_norm @ V, writes X as bf16 hi/lo.
// ---------------------------------------------------------------------------
__global__ void __launch_bounds__(256)
pv_mma(float* __restrict__ attn, const float* __restrict__ rinv,
       const __nv_bfloat16* __restrict__ Vth, const __nv_bfloat16* __restrict__ Vtl,
       __nv_bfloat16* __restrict__ Xh, __nv_bfloat16* __restrict__ Xl)
{
    const int bm = (gridDim.y - 1) - blockIdx.y;   // heavy tiles first
    const int z = blockIdx.z;
    const int b = z / H_, h = z % H_;
    extern __shared__ char smem[];
    const uint32_t sb = smem_u32(smem);
    const int tid = threadIdx.x, lane = tid & 31, wid = tid >> 5;
    const int wm = wid & 1, wn = wid >> 1;
    const int a0 = bm * 128;
    const int row = tid >> 1, sege = (tid & 1) * 16;

    float* Az = attn + (size_t)z * S_ * S_;
    const __nv_bfloat16* Vh = Vth + (size_t)z * DK_ * S_;
    const __nv_bfloat16* Vl = Vtl + (size_t)z * DK_ * S_;
    const int NCH = (bm + 1) * 4;        // causal truncation
    const float ri = rinv[(size_t)z * S_ + a0 + row];

    float acc[4][4][4];
#pragma unroll
    for (int i = 0; i < 4; i++)
#pragma unroll
        for (int j = 0; j < 4; j++)
#pragma unroll
            for (int k = 0; k < 4; k++) acc[i][j][k] = 0.0f;

    float4 pre[4];
    auto loadV = [&](int c, int s) {
        uint32_t so = sb + s * STG + (row * PADK + sege) * 2;
        const __nv_bfloat16* g;
        g = Vh + (size_t)row * S_ + c * 32 + sege;    // row = dk
        cpa16(so + SOFF_BH, g); cpa16(so + SOFF_BH + 16, g + 8);
        g = Vl + (size_t)row * S_ + c * 32 + sege;
        cpa16(so + SOFF_BL, g); cpa16(so + SOFF_BL + 16, g + 8);
    };
    auto loadA = [&](int c) {
        const float* g = Az + (size_t)(a0 + row) * S_ + c * 32 + sege;
#pragma unroll
        for (int j = 0; j < 4; ++j) pre[j] = *(const float4*)(g + j * 4);
    };
    auto storeA = [&](int c, int s) {
        char* p = smem + s * STG + (row * PADK + sege) * 2;
        float* gw = Az + (size_t)(a0 + row) * S_ + c * 32 + sege;
#pragma unroll
        for (int j = 0; j < 4; ++j) {
            float4 v = pre[j];
            v.x *= ri; v.y *= ri; v.z *= ri; v.w *= ri;
            *(float4*)(gw + j * 4) = v;               // normalized attn out
            __nv_bfloat16 h0 = __float2bfloat16(v.x);
            __nv_bfloat16 h1 = __float2bfloat16(v.y);
            __nv_bfloat16 h2 = __float2bfloat16(v.z);
            __nv_bfloat16 h3 = __float2bfloat16(v.w);
            __nv_bfloat16 l0 = __float2bfloat16(v.x - __bfloat162float(h0));
            __nv_bfloat16 l1 = __float2bfloat16(v.y - __bfloat162float(h1));
            __nv_bfloat16 l2 = __float2bfloat16(v.z - __bfloat162float(h2));
            __nv_bfloat16 l3 = __float2bfloat16(v.w - __bfloat162float(h3));
            *(__nv_bfloat162*)(p + SOFF_AH + j * 8)     = __nv_bfloat162(h0, h1);
            *(__nv_bfloat162*)(p + SOFF_AH + j * 8 + 4) = __nv_bfloat162(h2, h3);
            *(__nv_bfloat162*)(p + SOFF_AL + j * 8)     = __nv_bfloat162(l0, l1);
            *(__nv_bfloat162*)(p + SOFF_AL + j * 8 + 4) = __nv_bfloat162(l2, l3);
        }
    };

    loadV(0, 0); CP_COMMIT();
    loadA(0);
    for (int c = 0; c < NCH; ++c) {
        const int s = c & 1;
        storeA(c, s);
        if (c + 1 < NCH) { loadV(c + 1, s ^ 1); CP_COMMIT(); CP_WAIT1(); }
        else             { CP_WAIT0(); }
        __syncthreads();
        if (c + 1 < NCH) loadA(c + 1);
        mma_stage(sb + s * STG, acc, wm, wn, lane);
        __syncthreads();
    }

    // epilogue: X as bf16 hi/lo in [M, D] layout
#pragma unroll
    for (int mi = 0; mi < 4; ++mi) {
#pragma unroll
        for (int ni = 0; ni < 4; ++ni) {
            const int r = wm * 64 + mi * 16 + (lane >> 2);
            const int c = wn * 32 + ni * 8 + (lane & 3) * 2;
            const int m0 = a0 + r, m1 = m0 + 8;
            float v00 = acc[mi][ni][0], v01 = acc[mi][ni][1];
            float v10 = acc[mi][ni][2], v11 = acc[mi][ni][3];
            __nv_bfloat16 h00 = __float2bfloat16(v00);
            __nv_bfloat16 h01 = __float2bfloat16(v01);
            __nv_bfloat16 h10 = __float2bfloat16(v10);
            __nv_bfloat16 h11 = __float2bfloat16(v11);
            __nv_bfloat16 l00 = __float2bfloat16(v00 - __bfloat162float(h00));
            __nv_bfloat16 l01 = __float2bfloat16(v01 - __bfloat162float(h01));
            __nv_bfloat16 l10 = __float2bfloat16(v10 - __bfloat162float(h10));
            __nv_bfloat16 l11 = __float2bfloat16(v11 - __bfloat162float(h11));
            size_t i0 = ((size_t)b * S_ + m0) * D_ + h * DK_ + c;
            size_t i1 = ((size_t)b * S_ + m1) * D_ + h * DK_ + c;
            *(__nv_bfloat162*)&Xh[i0] = __nv_bfloat162(h00, h01);
            *(__nv_bfloat162*)&Xl[i0] = __nv_bfloat162(l00, l01);
            *(__nv_bfloat162*)&Xh[i1] = __nv_bfloat162(h10, h11);
            *(__nv_bfloat162*)&Xl[i1] = __nv_bfloat162(l10, l11);
        }
    }
}

// ---------------------------------------------------------------------------
// Launch
// ---------------------------------------------------------------------------
extern "C" void kernel_launch(void* const* d_in, const int* in_sizes, int n_in,
                              void* d_out, int out_size)
{
    const float* query = (const float*)d_in[0];
    const float* key   = (const float*)d_in[1];
    const float* value = (const float*)d_in[2];
    const float* Wq    = (const float*)d_in[3];
    const float* bq    = (const float*)d_in[4];
    const float* Wk    = (const float*)d_in[5];
    const float* bk    = (const float*)d_in[6];
    const float* Wv    = (const float*)d_in[7];
    const float* bv    = (const float*)d_in[8];
    const float* Wo    = (const float*)d_in[9];
    const float* bo    = (const float*)d_in[10];
    float* out = (float*)d_out;

    float *pfb, *ppsum, *prinv;
    cudaGetSymbolAddress((void**)&pfb,   g_attn_fb);
    cudaGetSymbolAddress((void**)&ppsum, g_psum);
    cudaGetSymbolAddress((void**)&prinv, g_rinv);

    __nv_bfloat16 *qi_h, *qi_l, *ki_h, *ki_l, *vi_h, *vi_l, *x_h, *x_l;
    __nv_bfloat16 *wq_h, *wq_l, *wk_h, *wk_l, *wv_h, *wv_l, *wo_h, *wo_l;
    __nv_bfloat16 *qh, *ql, *kh, *kl, *vth, *vtl;
    cudaGetSymbolAddress((void**)&qi_h, g_qi_h); cudaGetSymbolAddress((void**)&qi_l, g_qi_l);
    cudaGetSymbolAddress((void**)&ki_h, g_ki_h); cudaGetSymbolAddress((void**)&ki_l, g_ki_l);
    cudaGetSymbolAddress((void**)&vi_h, g_vi_h); cudaGetSymbolAddress((void**)&vi_l, g_vi_l);
    cudaGetSymbolAddress((void**)&x_h,  g_x_h);  cudaGetSymbolAddress((void**)&x_l,  g_x_l);
    cudaGetSymbolAddress((void**)&wq_h, g_wq_h); cudaGetSymbolAddress((void**)&wq_l, g_wq_l);
    cudaGetSymbolAddress((void**)&wk_h, g_wk_h); cudaGetSymbolAddress((void**)&wk_l, g_wk_l);
    cudaGetSymbolAddress((void**)&wv_h, g_wv_h); cudaGetSymbolAddress((void**)&wv_l, g_wv_l);
    cudaGetSymbolAddress((void**)&wo_h, g_wo_h); cudaGetSymbolAddress((void**)&wo_l, g_wo_l);
    cudaGetSymbolAddress((void**)&qh, g_qh);   cudaGetSymbolAddress((void**)&ql, g_ql);
    cudaGetSymbolAddress((void**)&kh, g_kh);   cudaGetSymbolAddress((void**)&kl, g_kl);
    cudaGetSymbolAddress((void**)&vth, g_vth); cudaGetSymbolAddress((void**)&vtl, g_vtl);

    float* attn = ((size_t)out_size >= OUT_N + ATTN_N) ? (out + OUT_N) : pfb;

    cudaFuncSetAttribute(gemm_mma<0>, cudaFuncAttributeMaxDynamicSharedMemorySize, DYN_SMEM);
    cudaFuncSetAttribute(gemm_mma<1>, cudaFuncAttributeMaxDynamicSharedMemorySize, DYN_SMEM);
    cudaFuncSetAttribute(gemm_mma<2>, cudaFuncAttributeMaxDynamicSharedMemorySize, DYN_SMEM);
    cudaFuncSetAttribute(scores_mma,  cudaFuncAttributeMaxDynamicSharedMemorySize, DYN_SMEM);
    cudaFuncSetAttribute(pv_mma,      cudaFuncAttributeMaxDynamicSharedMemorySize, DYN_SMEM);

    dim3 blk(256);
    const int IN4 = (M_ * D_) / 4;
    const int WN4 = (D_ * D_) / 4;
    dim3 gproj(D_ / 128, M_ / 128);   // (16, 32)

    // Launch order arranged so ncu's "-s 5 -c 1" captures gemm_mma<1> (launch #6).
    split_kernel<<<2048, blk>>>(query, qi_h, qi_l, IN4);               // 1
    split_kernel<<<2048, blk>>>(key,   ki_h, ki_l, IN4);               // 2
    split_kernel<<<2048, blk>>>(value, vi_h, vi_l, IN4);               // 3
    split_kernel<<<2048, blk>>>(Wq, wq_h, wq_l, WN4);                  // 4
    split_kernel<<<2048, blk>>>(Wk, wk_h, wk_l, WN4);                  // 5
    gemm_mma<1><<<gproj, blk, DYN_SMEM>>>(qi_h, qi_l, wq_h, wq_l, bq,  // 6 (profiled)
                                          nullptr, qh, ql);
    split_kernel<<<2048, blk>>>(Wv, wv_h, wv_l, WN4);                  // 7
    split_kernel<<<2048, blk>>>(Wo, wo_h, wo_l, WN4);                  // 8
    gemm_mma<1><<<gproj, blk, DYN_SMEM>>>(ki_h, ki_l, wk_h, wk_l, bk,  // 9
                                          nullptr, kh, kl);
    gemm_mma<2><<<gproj, blk, DYN_SMEM>>>(vi_h, vi_l, wv_h, wv_l, bv,  // 10
                                          nullptr, vth, vtl);

    // scores -> exp + per-tile row partials
    const float scale2 = (1.0f / sqrtf((float)DK_)) * 1.44269504088896f;
    dim3 gsc(S_ / 128, S_ / 128, B_ * H_);
    scores_mma<<<gsc, blk, DYN_SMEM>>>(qh, ql, kh, kl, attn, ppsum, scale2); // 11

    sumfin_kernel<<<B_ * H_ * S_ / 256, blk>>>(ppsum, prinv);          // 12
    zero_kernel<<<B_ * H_ * S_, blk>>>(attn);                          // 13

    // PV: normalizes attn in place + writes X bf16 hi/lo
    dim3 gpv(1, S_ / 128, B_ * H_);
    pv_mma<<<gpv, blk, DYN_SMEM>>>(attn, prinv, vth, vtl, x_h, x_l);   // 14

    // out = X @ Wo^T + bo
    gemm_mma<0><<<gproj, blk, DYN_SMEM>>>(x_h, x_l, wo_h, wo_l, bo,    // 15
                                          out, nullptr, nullptr);
}

// round 17
// speedup vs baseline: 2.2907x; 1.0465x over previous
#include <cuda_runtime.h>
#include <cuda_bf16.h>
#include <math.h>
#include <stdint.h>

// Problem constants (B=2, S=2048, D=2048, H=16, DK=128)
#define B_  2
#define S_  2048
#define D_  2048
#define H_  16
#define DK_ 128
#define M_  (B_ * S_)

static const size_t OUT_N  = (size_t)B_ * S_ * D_;        // 8388608
static const size_t ATTN_N = (size_t)B_ * H_ * S_ * S_;   // 134217728
#define BHSDK (B_ * H_ * S_ * DK_)                        // 8388608

// ---------------------------------------------------------------------------
// Scratch (__device__ globals; allocation-free contract)
// ---------------------------------------------------------------------------
__device__ float g_attn_fb[(size_t)B_ * H_ * S_ * S_];    // fallback scores
__device__ float g_psum[(size_t)B_ * H_ * S_ * 16];       // per-tile row partials

// bf16 split operands
__device__ __nv_bfloat16 g_qi_h[M_ * D_], g_qi_l[M_ * D_];   // input splits
__device__ __nv_bfloat16 g_ki_h[M_ * D_], g_ki_l[M_ * D_];
__device__ __nv_bfloat16 g_vi_h[M_ * D_], g_vi_l[M_ * D_];
__device__ __nv_bfloat16 g_x_h [M_ * D_], g_x_l [M_ * D_];   // X (PV out) splits
__device__ __nv_bfloat16 g_wq_h[D_ * D_], g_wq_l[D_ * D_];   // weight splits
__device__ __nv_bfloat16 g_wk_h[D_ * D_], g_wk_l[D_ * D_];
__device__ __nv_bfloat16 g_wv_h[D_ * D_], g_wv_l[D_ * D_];
__device__ __nv_bfloat16 g_wo_h[D_ * D_], g_wo_l[D_ * D_];
// projection outputs, bf16 split
__device__ __nv_bfloat16 g_qh[BHSDK], g_ql[BHSDK];           // [B,H,S,DK]
__device__ __nv_bfloat16 g_kh[BHSDK], g_kl[BHSDK];           // [B,H,S,DK]
__device__ __nv_bfloat16 g_vth[BHSDK], g_vtl[BHSDK];         // [B,H,DK,S]

// ---------------------------------------------------------------------------
// Baseline-ISA helpers (sm_80-level: cp.async / ldmatrix / mma.sync only)
// ---------------------------------------------------------------------------
__device__ __forceinline__ uint32_t smem_u32(const void* p) {
    uint32_t a;
    asm("{ .reg .u64 t; cvta.to.shared.u64 t, %1; cvt.u32.u64 %0, t; }"
        : "=r"(a) : "l"(p));
    return a;
}
__device__ __forceinline__ void cpa16(uint32_t saddr, const void* g) {
    asm volatile("cp.async.cg.shared.global [%0], [%1], 16;"
                 :: "r"(saddr), "l"(g));
}
#define CP_COMMIT() asm volatile("cp.async.commit_group;" ::: "memory")
#define CP_WAIT1()  asm volatile("cp.async.wait_group 1;" ::: "memory")
#define CP_WAIT0()  asm volatile("cp.async.wait_group 0;" ::: "memory")

__device__ __forceinline__ void ldmx4(uint32_t& r0, uint32_t& r1,
                                      uint32_t& r2, uint32_t& r3, uint32_t addr) {
    asm volatile("ldmatrix.sync.aligned.m8n8.x4.shared.b16 {%0,%1,%2,%3}, [%4];"
                 : "=r"(r0), "=r"(r1), "=r"(r2), "=r"(r3) : "r"(addr));
}
__device__ __forceinline__ void mma16816(float* c, uint32_t a0, uint32_t a1,
                                         uint32_t a2, uint32_t a3,
                                         uint32_t b0, uint32_t b1) {
    asm volatile(
        "mma.sync.aligned.m16n8k16.row.col.f32.bf16.bf16.f32 "
        "{%0,%1,%2,%3}, {%4,%5,%6,%7}, {%8,%9}, {%0,%1,%2,%3};"
        : "+f"(c[0]), "+f"(c[1]), "+f"(c[2]), "+f"(c[3])
        : "r"(a0), "r"(a1), "r"(a2), "r"(a3), "r"(b0), "r"(b1));
}

// Shared-stage layout: Ah | Al | Bh | Bl, each 128 rows x 32 bf16, PADK pad
#define PADK    40
#define SOFF_AH 0
#define SOFF_AL 10240
#define SOFF_BH 20480
#define SOFF_BL 30720
#define STG     40960
#define DYN_SMEM (2 * STG)   // 80KB

// 3-MMA fused compute on one stage: acc += Ah*Bh + Ah*Bl + Al*Bh
__device__ __forceinline__ void mma_stage(uint32_t sbase, float acc[4][4][4],
                                          int wm, int wn, int lane)
{
    uint32_t bh[4][4], bl[4][4];
#pragma unroll
    for (int ni = 0; ni < 4; ++ni) {
        uint32_t off = ((wn * 32 + ni * 8 + (lane & 7)) * PADK + (lane >> 3) * 8) * 2;
        ldmx4(bh[ni][0], bh[ni][1], bh[ni][2], bh[ni][3], sbase + SOFF_BH + off);
        ldmx4(bl[ni][0], bl[ni][1], bl[ni][2], bl[ni][3], sbase + SOFF_BL + off);
    }
#pragma unroll
    for (int k16 = 0; k16 < 2; ++k16) {
#pragma unroll
        for (int mi = 0; mi < 4; ++mi) {
            uint32_t off = ((wm * 64 + mi * 16 + (lane & 15)) * PADK
                            + (lane >> 4) * 8 + k16 * 16) * 2;
            uint32_t ah0, ah1, ah2, ah3, al0, al1, al2, al3;
            ldmx4(ah0, ah1, ah2, ah3, sbase + SOFF_AH + off);
            ldmx4(al0, al1, al2, al3, sbase + SOFF_AL + off);
#pragma unroll
            for (int ni = 0; ni < 4; ++ni) {
                mma16816(acc[mi][ni], ah0, ah1, ah2, ah3,
                         bh[ni][k16 * 2], bh[ni][k16 * 2 + 1]);
                mma16816(acc[mi][ni], ah0, ah1, ah2, ah3,
                         bl[ni][k16 * 2], bl[ni][k16 * 2 + 1]);
                mma16816(acc[mi][ni], al0, al1, al2, al3,
                         bh[ni][k16 * 2], bh[ni][k16 * 2 + 1]);
            }
        }
    }
}

// ---------------------------------------------------------------------------
// split body + merged split kernels (inputs x3, weights x4)
// ---------------------------------------------------------------------------
__device__ __forceinline__ void split_body(const float* __restrict__ x,
                                           __nv_bfloat16* __restrict__ hi,
                                           __nv_bfloat16* __restrict__ lo, int n4)
{
    int i = blockIdx.x * 256 + threadIdx.x;
    int stride = gridDim.x * 256;
    for (; i < n4; i += stride) {
        float4 v = ((const float4*)x)[i];
        __nv_bfloat16 h0 = __float2bfloat16(v.x);
        __nv_bfloat16 h1 = __float2bfloat16(v.y);
        __nv_bfloat16 h2 = __float2bfloat16(v.z);
        __nv_bfloat16 h3 = __float2bfloat16(v.w);
        __nv_bfloat16 l0 = __float2bfloat16(v.x - __bfloat162float(h0));
        __nv_bfloat16 l1 = __float2bfloat16(v.y - __bfloat162float(h1));
        __nv_bfloat16 l2 = __float2bfloat16(v.z - __bfloat162float(h2));
        __nv_bfloat16 l3 = __float2bfloat16(v.w - __bfloat162float(h3));
        ((__nv_bfloat162*)hi)[2 * i]     = __nv_bfloat162(h0, h1);
        ((__nv_bfloat162*)hi)[2 * i + 1] = __nv_bfloat162(h2, h3);
        ((__nv_bfloat162*)lo)[2 * i]     = __nv_bfloat162(l0, l1);
        ((__nv_bfloat162*)lo)[2 * i + 1] = __nv_bfloat162(l2, l3);
    }
}

__global__ void __launch_bounds__(256)
split3_kernel(const float* x0, const float* x1, const float* x2,
              __nv_bfloat16* h0, __nv_bfloat16* l0,
              __nv_bfloat16* h1, __nv_bfloat16* l1,
              __nv_bfloat16* h2, __nv_bfloat16* l2, int n4)
{
    const int z = blockIdx.y;
    const float* x = (z == 0) ? x0 : (z == 1) ? x1 : x2;
    __nv_bfloat16* hi = (z == 0) ? h0 : (z == 1) ? h1 : h2;
    __nv_bfloat16* lo = (z == 0) ? l0 : (z == 1) ? l1 : l2;
    split_body(x, hi, lo, n4);
}

__global__ void __launch_bounds__(256)
split4_kernel(const float* x0, const float* x1, const float* x2, const float* x3,
              __nv_bfloat16* h0, __nv_bfloat16* l0,
              __nv_bfloat16* h1, __nv_bfloat16* l1,
              __nv_bfloat16* h2, __nv_bfloat16* l2,
              __nv_bfloat16* h3, __nv_bfloat16* l3, int n4)
{
    const int z = blockIdx.y;
    const float* x = (z == 0) ? x0 : (z == 1) ? x1 : (z == 2) ? x2 : x3;
    __nv_bfloat16* hi = (z == 0) ? h0 : (z == 1) ? h1 : (z == 2) ? h2 : h3;
    __nv_bfloat16* lo = (z == 0) ? l0 : (z == 1) ? l1 : (z == 2) ? l2 : l3;
    split_body(x, hi, lo, n4);
}

// ---------------------------------------------------------------------------
// GEMM core (shared by QKV and O kernels)
// mode 0: fp32 [M,D]; mode 1: bf16 hi/lo [B,H,S,DK]; mode 2: bf16 hi/lo [B,H,DK,S]
// ---------------------------------------------------------------------------
__device__ __forceinline__ void gemm_body(
    const __nv_bfloat16* __restrict__ Ahi, const __nv_bfloat16* __restrict__ Alo,
    const __nv_bfloat16* __restrict__ Whi, const __nv_bfloat16* __restrict__ Wlo,
    const float* __restrict__ bias, float* __restrict__ Cf,
    __nv_bfloat16* __restrict__ Ch, __nv_bfloat16* __restrict__ Cl, int mode,
    char* smem)
{
    const uint32_t sb = smem_u32(smem);
    const int tid = threadIdx.x, lane = tid & 31, wid = tid >> 5;
    const int wm = wid & 1, wn = wid >> 1;
    const int a0 = blockIdx.y * 128, n0 = blockIdx.x * 128;
    const int row = tid >> 1, sege = (tid & 1) * 16;

    float acc[4][4][4];
#pragma unroll
    for (int i = 0; i < 4; i++)
#pragma unroll
        for (int j = 0; j < 4; j++)
#pragma unroll
            for (int k = 0; k < 4; k++) acc[i][j][k] = 0.0f;

    auto load_stage = [&](int st) {
        const int s = st & 1, k0 = st * 32;
        uint32_t so = sb + s * STG + (row * PADK + sege) * 2;
        const __nv_bfloat16* g;
        g = Ahi + (size_t)(a0 + row) * D_ + k0 + sege;
        cpa16(so + SOFF_AH, g); cpa16(so + SOFF_AH + 16, g + 8);
        g = Alo + (size_t)(a0 + row) * D_ + k0 + sege;
        cpa16(so + SOFF_AL, g); cpa16(so + SOFF_AL + 16, g + 8);
        g = Whi + (size_t)(n0 + row) * D_ + k0 + sege;
        cpa16(so + SOFF_BH, g); cpa16(so + SOFF_BH + 16, g + 8);
        g = Wlo + (size_t)(n0 + row) * D_ + k0 + sege;
        cpa16(so + SOFF_BL, g); cpa16(so + SOFF_BL + 16, g + 8);
    };

    const int NCH = D_ / 32;   // 64
    load_stage(0); CP_COMMIT();
    load_stage(1); CP_COMMIT();
    for (int st = 0; st < NCH; ++st) {
        const int s = st & 1;
        if (st + 1 < NCH) CP_WAIT1(); else CP_WAIT0();
        __syncthreads();
        mma_stage(sb + s * STG, acc, wm, wn, lane);
        __syncthreads();
        if (st + 2 < NCH) { load_stage(st + 2); CP_COMMIT(); }
    }

#pragma unroll
    for (int mi = 0; mi < 4; ++mi) {
#pragma unroll
        for (int ni = 0; ni < 4; ++ni) {
            const int r = wm * 64 + mi * 16 + (lane >> 2);
            const int c = wn * 32 + ni * 8 + (lane & 3) * 2;
            const int n = n0 + c;
            const int m0 = a0 + r, m1 = m0 + 8;
            float v00 = acc[mi][ni][0] + bias[n];
            float v01 = acc[mi][ni][1] + bias[n + 1];
            float v10 = acc[mi][ni][2] + bias[n];
            float v11 = acc[mi][ni][3] + bias[n + 1];
            if (mode == 0) {
                *(float2*)&Cf[(size_t)m0 * D_ + n] = make_float2(v00, v01);
                *(float2*)&Cf[(size_t)m1 * D_ + n] = make_float2(v10, v11);
            } else {
                const int h = n >> 7, dk = n & 127;
                const int b0v = m0 >> 11, s0 = m0 & (S_ - 1);
                const int b1v = m1 >> 11, s1 = m1 & (S_ - 1);
                __nv_bfloat16 h00 = __float2bfloat16(v00);
                __nv_bfloat16 h01 = __float2bfloat16(v01);
                __nv_bfloat16 h10 = __float2bfloat16(v10);
                __nv_bfloat16 h11 = __float2bfloat16(v11);
                __nv_bfloat16 l00 = __float2bfloat16(v00 - __bfloat162float(h00));
                __nv_bfloat16 l01 = __float2bfloat16(v01 - __bfloat162float(h01));
                __nv_bfloat16 l10 = __float2bfloat16(v10 - __bfloat162float(h10));
                __nv_bfloat16 l11 = __float2bfloat16(v11 - __bfloat162float(h11));
                if (mode == 1) {
                    size_t i0 = (((size_t)b0v * H_ + h) * S_ + s0) * DK_ + dk;
                    size_t i1 = (((size_t)b1v * H_ + h) * S_ + s1) * DK_ + dk;
                    *(__nv_bfloat162*)&Ch[i0] = __nv_bfloat162(h00, h01);
                    *(__nv_bfloat162*)&Cl[i0] = __nv_bfloat162(l00, l01);
                    *(__nv_bfloat162*)&Ch[i1] = __nv_bfloat162(h10, h11);
                    *(__nv_bfloat162*)&Cl[i1] = __nv_bfloat162(l10, l11);
                } else {
                    size_t t00 = (((size_t)b0v * H_ + h) * DK_ + dk)     * S_ + s0;
                    size_t t01 = (((size_t)b0v * H_ + h) * DK_ + dk + 1) * S_ + s0;
                    size_t t10 = (((size_t)b1v * H_ + h) * DK_ + dk)     * S_ + s1;
                    size_t t11 = (((size_t)b1v * H_ + h) * DK_ + dk + 1) * S_ + s1;
                    Ch[t00] = h00; Cl[t00] = l00;
                    Ch[t01] = h01; Cl[t01] = l01;
                    Ch[t10] = h10; Cl[t10] = l10;
                    Ch[t11] = h11; Cl[t11] = l11;
                }
            }
        }
    }
}

// QKV merged: grid.z = 0(Q),1(K) -> mode1 ; 2(V) -> mode2
__global__ void __launch_bounds__(256)
gemm_qkv(const __nv_bfloat16* a0h, const __nv_bfloat16* a0l,
         const __nv_bfloat16* a1h, const __nv_bfloat16* a1l,
         const __nv_bfloat16* a2h, const __nv_bfloat16* a2l,
         const __nv_bfloat16* w0h, const __nv_bfloat16* w0l,
         const __nv_bfloat16* w1h, const __nv_bfloat16* w1l,
         const __nv_bfloat16* w2h, const __nv_bfloat16* w2l,
         const float* b0, const float* b1, const float* b2,
         __nv_bfloat16* c0h, __nv_bfloat16* c0l,
         __nv_bfloat16* c1h, __nv_bfloat16* c1l,
         __nv_bfloat16* c2h, __nv_bfloat16* c2l)
{
    extern __shared__ char smem[];
    const int z = blockIdx.z;
    const __nv_bfloat16* Ah = (z == 0) ? a0h : (z == 1) ? a1h : a2h;
    const __nv_bfloat16* Al = (z == 0) ? a0l : (z == 1) ? a1l : a2l;
    const __nv_bfloat16* Wh = (z == 0) ? w0h : (z == 1) ? w1h : w2h;
    const __nv_bfloat16* Wl = (z == 0) ? w0l : (z == 1) ? w1l : w2l;
    const float* bias = (z == 0) ? b0 : (z == 1) ? b1 : b2;
    __nv_bfloat16* Ch = (z == 0) ? c0h : (z == 1) ? c1h : c2h;
    __nv_bfloat16* Cl = (z == 0) ? c0l : (z == 1) ? c1l : c2l;
    gemm_body(Ah, Al, Wh, Wl, bias, nullptr, Ch, Cl, (z < 2) ? 1 : 2, smem);
}

// O projection: fp32 out
__global__ void __launch_bounds__(256)
gemm_o(const __nv_bfloat16* Ah, const __nv_bfloat16* Al,
       const __nv_bfloat16* Wh, const __nv_bfloat16* Wl,
       const float* bias, float* Cf)
{
    extern __shared__ char smem[];
    gemm_body(Ah, Al, Wh, Wl, bias, Cf, nullptr, nullptr, 0, smem);
}

// ---------------------------------------------------------------------------
// K2: scores via mma.sync — lower tiles write exp(score) + row partials;
// upper tiles (bn>bm) write their zero block (replaces zero_kernel).
// ---------------------------------------------------------------------------
__global__ void __launch_bounds__(256)
scores_mma(const __nv_bfloat16* __restrict__ Qh, const __nv_bfloat16* __restrict__ Ql,
           const __nv_bfloat16* __restrict__ Kh, const __nv_bfloat16* __restrict__ Kl,
           float* __restrict__ attn, float* __restrict__ psum, float scale2)
{
    const int bm = blockIdx.y, bn = blockIdx.x, z = blockIdx.z;
    float* C = attn + (size_t)z * S_ * S_;
    const int tid = threadIdx.x;

    if (bn > bm) {
        // zero tile: 128 rows x 128 cols; 2 threads per row, 16 float4 each
        const int r = tid >> 1, c4 = (tid & 1) * 16;
        float4* p = (float4*)(C + (size_t)(bm * 128 + r) * S_ + bn * 128) + c4;
        const float4 z4 = make_float4(0.f, 0.f, 0.f, 0.f);
#pragma unroll
        for (int j = 0; j < 16; ++j) p[j] = z4;
        return;
    }

    extern __shared__ char smem[];
    __shared__ float sps[4][128];
    const uint32_t sb = smem_u32(smem);
    const int lane = tid & 31, wid = tid >> 5;
    const int wm = wid & 1, wn = wid >> 1;
    const int a0 = bm * 128, n0 = bn * 128;
    const int row = tid >> 1, sege = (tid & 1) * 16;

    const __nv_bfloat16* Qhz = Qh + (size_t)z * S_ * DK_;
    const __nv_bfloat16* Qlz = Ql + (size_t)z * S_ * DK_;
    const __nv_bfloat16* Khz = Kh + (size_t)z * S_ * DK_;
    const __nv_bfloat16* Klz = Kl + (size_t)z * S_ * DK_;

    float acc[4][4][4];
#pragma unroll
    for (int i = 0; i < 4; i++)
#pragma unroll
        for (int j = 0; j < 4; j++)
#pragma unroll
            for (int k = 0; k < 4; k++) acc[i][j][k] = 0.0f;

    auto load_stage = [&](int st) {
        const int s = st & 1, k0 = st * 32;
        uint32_t so = sb + s * STG + (row * PADK + sege) * 2;
        const __nv_bfloat16* g;
        g = Qhz + (size_t)(a0 + row) * DK_ + k0 + sege;
        cpa16(so + SOFF_AH, g); cpa16(so + SOFF_AH + 16, g + 8);
        g = Qlz + (size_t)(a0 + row) * DK_ + k0 + sege;
        cpa16(so + SOFF_AL, g); cpa16(so + SOFF_AL + 16, g + 8);
        g = Khz + (size_t)(n0 + row) * DK_ + k0 + sege;
        cpa16(so + SOFF_BH, g); cpa16(so + SOFF_BH + 16, g + 8);
        g = Klz + (size_t)(n0 + row) * DK_ + k0 + sege;
        cpa16(so + SOFF_BL, g); cpa16(so + SOFF_BL + 16, g + 8);
    };

    const int NCH = DK_ / 32;  // 4
    load_stage(0); CP_COMMIT();
    load_stage(1); CP_COMMIT();
    for (int st = 0; st < NCH; ++st) {
        const int s = st & 1;
        if (st + 1 < NCH) CP_WAIT1(); else CP_WAIT0();
        __syncthreads();
        mma_stage(sb + s * STG, acc, wm, wn, lane);
        __syncthreads();
        if (st + 2 < NCH) { load_stage(st + 2); CP_COMMIT(); }
    }

    float rs0[4] = {0, 0, 0, 0}, rs1[4] = {0, 0, 0, 0};
#pragma unroll
    for (int mi = 0; mi < 4; ++mi) {
#pragma unroll
        for (int ni = 0; ni < 4; ++ni) {
            const int r = wm * 64 + mi * 16 + (lane >> 2);
            const int c = wn * 32 + ni * 8 + (lane & 3) * 2;
            const int m0 = a0 + r, m1 = m0 + 8;
            const int n = n0 + c;
            float e00 = (n     <= m0) ? exp2f(acc[mi][ni][0] * scale2) : 0.0f;
            float e01 = (n + 1 <= m0) ? exp2f(acc[mi][ni][1] * scale2) : 0.0f;
            float e10 = (n     <= m1) ? exp2f(acc[mi][ni][2] * scale2) : 0.0f;
            float e11 = (n + 1 <= m1) ? exp2f(acc[mi][ni][3] * scale2) : 0.0f;
            *(float2*)&C[(size_t)m0 * S_ + n] = make_float2(e00, e01);
            *(float2*)&C[(size_t)m1 * S_ + n] = make_float2(e10, e11);
            rs0[mi] += e00 + e01;
            rs1[mi] += e10 + e11;
        }
    }
#pragma unroll
    for (int mi = 0; mi < 4; ++mi) {
        float a = rs0[mi], b = rs1[mi];
        a += __shfl_xor_sync(0xffffffffu, a, 1);
        a += __shfl_xor_sync(0xffffffffu, a, 2);
        b += __shfl_xor_sync(0xffffffffu, b, 1);
        b += __shfl_xor_sync(0xffffffffu, b, 2);
        if ((lane & 3) == 0) {
            int r0 = wm * 64 + mi * 16 + (lane >> 2);
            sps[wn][r0]     = a;
            sps[wn][r0 + 8] = b;
        }
    }
    __syncthreads();
    if (tid < 128) {
        float s = sps[0][tid] + sps[1][tid] + sps[2][tid] + sps[3][tid];
        psum[((size_t)z * S_ + a0 + tid) * 16 + bn] = s;
    }
}

// ---------------------------------------------------------------------------
// K4: PV — computes rinv inline from psum, normalizes attn in place,
// X = attn_norm @ V written as bf16 hi/lo.
// ---------------------------------------------------------------------------
__global__ void __launch_bounds__(256)
pv_mma(float* __restrict__ attn, const float* __restrict__ psum,
       const __nv_bfloat16* __restrict__ Vth, const __nv_bfloat16* __restrict__ Vtl,
       __nv_bfloat16* __restrict__ Xh, __nv_bfloat16* __restrict__ Xl)
{
    const int bm = (gridDim.y - 1) - blockIdx.y;   // heavy tiles first
    const int z = blockIdx.z;
    const int b = z / H_, h = z % H_;
    extern __shared__ char smem[];
    const uint32_t sb = smem_u32(smem);
    const int tid = threadIdx.x, lane = tid & 31, wid = tid >> 5;
    const int wm = wid & 1, wn = wid >> 1;
    const int a0 = bm * 128;
    const int row = tid >> 1, sege = (tid & 1) * 16;

    float* Az = attn + (size_t)z * S_ * S_;
    const __nv_bfloat16* Vh = Vth + (size_t)z * DK_ * S_;
    const __nv_bfloat16* Vl = Vtl + (size_t)z * DK_ * S_;
    const int NCH = (bm + 1) * 4;        // causal truncation

    // inline row-sum finalize (deterministic tile order, nt = bm+1 tiles)
    float rsum = 0.0f;
    {
        const float* pp = psum + ((size_t)z * S_ + a0 + row) * 16;
        for (int i = 0; i <= bm; ++i) rsum += pp[i];
    }
    const float ri = 1.0f / rsum;

    float acc[4][4][4];
#pragma unroll
    for (int i = 0; i < 4; i++)
#pragma unroll
        for (int j = 0; j < 4; j++)
#pragma unroll
            for (int k = 0; k < 4; k++) acc[i][j][k] = 0.0f;

    float4 pre[4];
    auto loadV = [&](int c, int s) {
        uint32_t so = sb + s * STG + (row * PADK + sege) * 2;
        const __nv_bfloat16* g;
        g = Vh + (size_t)row * S_ + c * 32 + sege;    // row = dk
        cpa16(so + SOFF_BH, g); cpa16(so + SOFF_BH + 16, g + 8);
        g = Vl + (size_t)row * S_ + c * 32 + sege;
        cpa16(so + SOFF_BL, g); cpa16(so + SOFF_BL + 16, g + 8);
    };
    auto loadA = [&](int c) {
        const float* g = Az + (size_t)(a0 + row) * S_ + c * 32 + sege;
#pragma unroll
        for (int j = 0; j < 4; ++j) pre[j] = *(const float4*)(g + j * 4);
    };
    auto storeA = [&](int c, int s) {
        char* p = smem + s * STG + (row * PADK + sege) * 2;
        float* gw = Az + (size_t)(a0 + row) * S_ + c * 32 + sege;
#pragma unroll
        for (int j = 0; j < 4; ++j) {
            float4 v = pre[j];
            v.x *= ri; v.y *= ri; v.z *= ri; v.w *= ri;
            *(float4*)(gw + j * 4) = v;               // normalized attn out
            __nv_bfloat16 h0 = __float2bfloat16(v.x);
            __nv_bfloat16 h1 = __float2bfloat16(v.y);
            __nv_bfloat16 h2 = __float2bfloat16(v.z);
            __nv_bfloat16 h3 = __float2bfloat16(v.w);
            __nv_bfloat16 l0 = __float2bfloat16(v.x - __bfloat162float(h0));
            __nv_bfloat16 l1 = __float2bfloat16(v.y - __bfloat162float(h1));
            __nv_bfloat16 l2 = __float2bfloat16(v.z - __bfloat162float(h2));
            __nv_bfloat16 l3 = __float2bfloat16(v.w - __bfloat162float(h3));
            *(__nv_bfloat162*)(p + SOFF_AH + j * 8)     = __nv_bfloat162(h0, h1);
            *(__nv_bfloat162*)(p + SOFF_AH + j * 8 + 4) = __nv_bfloat162(h2, h3);
            *(__nv_bfloat162*)(p + SOFF_AL + j * 8)     = __nv_bfloat162(l0, l1);
            *(__nv_bfloat162*)(p + SOFF_AL + j * 8 + 4) = __nv_bfloat162(l2, l3);
        }
    };

    loadV(0, 0); CP_COMMIT();
    loadA(0);
    for (int c = 0; c < NCH; ++c) {
        const int s = c & 1;
        storeA(c, s);
        if (c + 1 < NCH) { loadV(c + 1, s ^ 1); CP_COMMIT(); CP_WAIT1(); }
        else             { CP_WAIT0(); }
        __syncthreads();
        if (c + 1 < NCH) loadA(c + 1);
        mma_stage(sb + s * STG, acc, wm, wn, lane);
        __syncthreads();
    }

#pragma unroll
    for (int mi = 0; mi < 4; ++mi) {
#pragma unroll
        for (int ni = 0; ni < 4; ++ni) {
            const int r = wm * 64 + mi * 16 + (lane >> 2);
            const int c = wn * 32 + ni * 8 + (lane & 3) * 2;
            const int m0 = a0 + r, m1 = m0 + 8;
            float v00 = acc[mi][ni][0], v01 = acc[mi][ni][1];
            float v10 = acc[mi][ni][2], v11 = acc[mi][ni][3];
            __nv_bfloat16 h00 = __float2bfloat16(v00);
            __nv_bfloat16 h01 = __float2bfloat16(v01);
            __nv_bfloat16 h10 = __float2bfloat16(v10);
            __nv_bfloat16 h11 = __float2bfloat16(v11);
            __nv_bfloat16 l00 = __float2bfloat16(v00 - __bfloat162float(h00));
            __nv_bfloat16 l01 = __float2bfloat16(v01 - __bfloat162float(h01));
            __nv_bfloat16 l10 = __float2bfloat16(v10 - __bfloat162float(h10));
            __nv_bfloat16 l11 = __float2bfloat16(v11 - __bfloat162float(h11));
            size_t i0 = ((size_t)b * S_ + m0) * D_ + h * DK_ + c;
            size_t i1 = ((size_t)b * S_ + m1) * D_ + h * DK_ + c;
            *(__nv_bfloat162*)&Xh[i0] = __nv_bfloat162(h00, h01);
            *(__nv_bfloat162*)&Xl[i0] = __nv_bfloat162(l00, l01);
            *(__nv_bfloat162*)&Xh[i1] = __nv_bfloat162(h10, h11);
            *(__nv_bfloat162*)&Xl[i1] = __nv_bfloat162(l10, l11);
        }
    }
}

// ---------------------------------------------------------------------------
// Launch  (6 launches total)
// ---------------------------------------------------------------------------
extern "C" void kernel_launch(void* const* d_in, const int* in_sizes, int n_in,
                              void* d_out, int out_size)
{
    const float* query = (const float*)d_in[0];
    const float* key   = (const float*)d_in[1];
    const float* value = (const float*)d_in[2];
    const float* Wq    = (const float*)d_in[3];
    const float* bq    = (const float*)d_in[4];
    const float* Wk    = (const float*)d_in[5];
    const float* bk    = (const float*)d_in[6];
    const float* Wv    = (const float*)d_in[7];
    const float* bv    = (const float*)d_in[8];
    const float* Wo    = (const float*)d_in[9];
    const float* bo    = (const float*)d_in[10];
    float* out = (float*)d_out;

    float *pfb, *ppsum;
    cudaGetSymbolAddress((void**)&pfb,   g_attn_fb);
    cudaGetSymbolAddress((void**)&ppsum, g_psum);

    __nv_bfloat16 *qi_h, *qi_l, *ki_h, *ki_l, *vi_h, *vi_l, *x_h, *x_l;
    __nv_bfloat16 *wq_h, *wq_l, *wk_h, *wk_l, *wv_h, *wv_l, *wo_h, *wo_l;
    __nv_bfloat16 *qh, *ql, *kh, *kl, *vth, *vtl;
    cudaGetSymbolAddress((void**)&qi_h, g_qi_h); cudaGetSymbolAddress((void**)&qi_l, g_qi_l);
    cudaGetSymbolAddress((void**)&ki_h, g_ki_h); cudaGetSymbolAddress((void**)&ki_l, g_ki_l);
    cudaGetSymbolAddress((void**)&vi_h, g_vi_h); cudaGetSymbolAddress((void**)&vi_l, g_vi_l);
    cudaGetSymbolAddress((void**)&x_h,  g_x_h);  cudaGetSymbolAddress((void**)&x_l,  g_x_l);
    cudaGetSymbolAddress((void**)&wq_h, g_wq_h); cudaGetSymbolAddress((void**)&wq_l, g_wq_l);
    cudaGetSymbolAddress((void**)&wk_h, g_wk_h); cudaGetSymbolAddress((void**)&wk_l, g_wk_l);
    cudaGetSymbolAddress((void**)&wv_h, g_wv_h); cudaGetSymbolAddress((void**)&wv_l, g_wv_l);
    cudaGetSymbolAddress((void**)&wo_h, g_wo_h); cudaGetSymbolAddress((void**)&wo_l, g_wo_l);
    cudaGetSymbolAddress((void**)&qh, g_qh);   cudaGetSymbolAddress((void**)&ql, g_ql);
    cudaGetSymbolAddress((void**)&kh, g_kh);   cudaGetSymbolAddress((void**)&kl, g_kl);
    cudaGetSymbolAddress((void**)&vth, g_vth); cudaGetSymbolAddress((void**)&vtl, g_vtl);

    float* attn = ((size_t)out_size >= OUT_N + ATTN_N) ? (out + OUT_N) : pfb;

    cudaFuncSetAttribute(gemm_qkv,   cudaFuncAttributeMaxDynamicSharedMemorySize, DYN_SMEM);
    cudaFuncSetAttribute(gemm_o,     cudaFuncAttributeMaxDynamicSharedMemorySize, DYN_SMEM);
    cudaFuncSetAttribute(scores_mma, cudaFuncAttributeMaxDynamicSharedMemorySize, DYN_SMEM);
    cudaFuncSetAttribute(pv_mma,     cudaFuncAttributeMaxDynamicSharedMemorySize, DYN_SMEM);

    dim3 blk(256);
    const int IN4 = (M_ * D_) / 4;
    const int WN4 = (D_ * D_) / 4;

    // 1) input splits (q,k,v)
    split3_kernel<<<dim3(1024, 3), blk>>>(query, key, value,
                                          qi_h, qi_l, ki_h, ki_l, vi_h, vi_l, IN4);
    // 2) weight splits (Wq,Wk,Wv,Wo)
    split4_kernel<<<dim3(2048, 4), blk>>>(Wq, Wk, Wv, Wo,
                                          wq_h, wq_l, wk_h, wk_l,
                                          wv_h, wv_l, wo_h, wo_l, WN4);
    // 3) QKV projections merged (grid.z: 0=Q,1=K,2=V)
    dim3 gqkv(D_ / 128, M_ / 128, 3);
    gemm_qkv<<<gqkv, blk, DYN_SMEM>>>(qi_h, qi_l, ki_h, ki_l, vi_h, vi_l,
                                      wq_h, wq_l, wk_h, wk_l, wv_h, wv_l,
                                      bq, bk, bv,
                                      qh, ql, kh, kl, vth, vtl);
    // 4) scores (exp + partials; upper tiles write zeros)
    const float scale2 = (1.0f / sqrtf((float)DK_)) * 1.44269504088896f;
    dim3 gsc(S_ / 128, S_ / 128, B_ * H_);
    scores_mma<<<gsc, blk, DYN_SMEM>>>(qh, ql, kh, kl, attn, ppsum, scale2);
    // 5) PV (inline rinv, in-place normalize, X bf16 hi/lo)
    dim3 gpv(1, S_ / 128, B_ * H_);
    pv_mma<<<gpv, blk, DYN_SMEM>>>(attn, ppsum, vth, vtl, x_h, x_l);
    // 6) out = X @ Wo^T + bo
    dim3 gproj(D_ / 128, M_ / 128);
    gemm_o<<<gproj, blk, DYN_SMEM>>>(x_h, x_l, wo_h, wo_l, bo, out);
}